// round 2
// baseline (speedup 1.0000x reference)
#include <cuda_runtime.h>
#include <math.h>

// Problem constants
#define N_PTS 32768
#define D_DIM 512
#define M_FEAT 512
#define KEPS 0.001f
#define NSTAB 1e-6f

#define SPLITK 32
#define KCHUNK (N_PTS / SPLITK)      // 1024
#define CS_BLOCKS 128
#define CS_ROWS (N_PTS / CS_BLOCKS)  // 256

// ---------------- scratch (static device globals; no allocations) ----------------
__device__ float g_Pq[D_DIM * M_FEAT];          // Wq @ proj^T
__device__ float g_Pk[D_DIM * M_FEAT];          // Wk @ proj^T
__device__ float g_cq[M_FEAT];                  // bq @ proj^T
__device__ float g_ck[M_FEAT];                  // bk @ proj^T
__device__ float g_qp[N_PTS * M_FEAT];          // q_prime  (64 MB)
__device__ float g_kp[N_PTS * M_FEAT];          // k_prime  (64 MB)
__device__ float g_ks_part[CS_BLOCKS * M_FEAT];
__device__ float g_ks[M_FEAT];                  // colsum(k_prime)
__device__ float g_kvpart[SPLITK * M_FEAT * D_DIM];  // 32 MB split-K partials
__device__ float g_kv[M_FEAT * D_DIM];
__device__ float g_invden[N_PTS];

// ---------------- generic tiled SGEMM body ----------------
// 128x128 block tile, K-step 8, 8x8 per-thread microtile, 256 threads.
#define BM 128
#define BN 128
#define BK 8
#define TM 8
#define TN 8

// LAYOUT: 0 = NN  (A[MxK] row-major, B[KxN] row-major)
//         1 = TN  (A[KxM] row-major, B[KxN] row-major)   -> C = A^T B
//         2 = NT  (A[MxK] row-major, B[NxK] row-major)   -> C = A B^T
// EPI:    0 = none
//         1 = relu(acc + ev[col]) + KEPS
//         2 = acc * ev[row]
template<int LAYOUT, int EPI>
__device__ __forceinline__ void sgemm_body(
    const float* __restrict__ A, const float* __restrict__ B,
    float* __restrict__ C, const float* __restrict__ ev,
    int Nc, int ldA, int ldB, int kBeg, int kEnd)
{
    __shared__ float As[BK][BM];
    __shared__ float Bs[BK][BN];
    const int tid = threadIdx.x;
    const int tx = tid & 15;
    const int ty = tid >> 4;
    const int rowBase = blockIdx.y * BM;
    const int colBase = blockIdx.x * BN;

    // K-major load pattern (operand stored with K contiguous): transpose into smem
    const int rA = tid >> 1;          // 0..127
    const int cA = (tid & 1) * 4;     // 0 or 4
    // MN-major load pattern (operand stored with M/N contiguous): direct into smem
    const int rK = tid >> 5;          // 0..7
    const int cK = (tid & 31) * 4;    // 0..124

    float acc[TM][TN];
#pragma unroll
    for (int i = 0; i < TM; i++)
#pragma unroll
        for (int j = 0; j < TN; j++) acc[i][j] = 0.f;

    auto loadA = [&](int k) -> float4 {
        if (LAYOUT == 1) return *(const float4*)(A + (k + rK) * ldA + rowBase + cK);
        else             return *(const float4*)(A + (rowBase + rA) * ldA + k + cA);
    };
    auto loadB = [&](int k) -> float4 {
        if (LAYOUT == 2) return *(const float4*)(B + (colBase + rA) * ldB + k + cA);
        else             return *(const float4*)(B + (k + rK) * ldB + colBase + cK);
    };

    float4 av = loadA(kBeg);
    float4 bv = loadB(kBeg);

    for (int kb = kBeg; kb < kEnd; kb += BK) {
        __syncthreads();  // previous tile fully consumed
        if (LAYOUT == 1) {
            *(float4*)&As[rK][cK] = av;
        } else {
            As[cA + 0][rA] = av.x; As[cA + 1][rA] = av.y;
            As[cA + 2][rA] = av.z; As[cA + 3][rA] = av.w;
        }
        if (LAYOUT == 2) {
            Bs[cA + 0][rA] = bv.x; Bs[cA + 1][rA] = bv.y;
            Bs[cA + 2][rA] = bv.z; Bs[cA + 3][rA] = bv.w;
        } else {
            *(float4*)&Bs[rK][cK] = bv;
        }
        __syncthreads();

        if (kb + BK < kEnd) {       // prefetch next global tile while computing
            av = loadA(kb + BK);
            bv = loadB(kb + BK);
        }

#pragma unroll
        for (int k = 0; k < BK; k++) {
            float4 a0 = *(const float4*)&As[k][ty * TM];
            float4 a1 = *(const float4*)&As[k][ty * TM + 4];
            float4 b0 = *(const float4*)&Bs[k][tx * TN];
            float4 b1 = *(const float4*)&Bs[k][tx * TN + 4];
            float a[TM] = {a0.x, a0.y, a0.z, a0.w, a1.x, a1.y, a1.z, a1.w};
            float b[TN] = {b0.x, b0.y, b0.z, b0.w, b1.x, b1.y, b1.z, b1.w};
#pragma unroll
            for (int i = 0; i < TM; i++)
#pragma unroll
                for (int j = 0; j < TN; j++)
                    acc[i][j] = fmaf(a[i], b[j], acc[i][j]);
        }
    }

    // epilogue
#pragma unroll
    for (int i = 0; i < TM; i++) {
        const int row = rowBase + ty * TM + i;
        const float sc = (EPI == 2) ? ev[row] : 1.f;
        float o[TN];
#pragma unroll
        for (int j = 0; j < TN; j++) {
            float v = acc[i][j];
            if (EPI == 1) v = fmaxf(v + ev[colBase + tx * TN + j], 0.f) + KEPS;
            if (EPI == 2) v = v * sc;
            o[j] = v;
        }
        float* cp = C + row * Nc + colBase + tx * TN;
        *(float4*)(cp)     = make_float4(o[0], o[1], o[2], o[3]);
        *(float4*)(cp + 4) = make_float4(o[4], o[5], o[6], o[7]);
    }
}

// ---------------- wrappers ----------------

// Pq = Wq @ proj^T, Pk = Wk @ proj^T   (NT, z selects q/k)
__global__ void __launch_bounds__(256) k_proj(const float* __restrict__ Wq,
                                              const float* __restrict__ Wk,
                                              const float* __restrict__ proj) {
    const float* A = blockIdx.z ? Wk : Wq;
    float* C = blockIdx.z ? g_Pk : g_Pq;
    sgemm_body<2, 0>(A, proj, C, nullptr, M_FEAT, D_DIM, D_DIM, 0, D_DIM);
}

// cq = bq @ proj^T, ck = bk @ proj^T   (tiny)
__global__ void k_bias(const float* __restrict__ bq, const float* __restrict__ bk,
                       const float* __restrict__ proj) {
    int m = blockIdx.x * blockDim.x + threadIdx.x;
    const float* b = blockIdx.y ? bk : bq;
    float* c = blockIdx.y ? g_ck : g_cq;
    float s = 0.f;
    for (int j = 0; j < D_DIM; j++) s += b[j] * proj[m * D_DIM + j];
    c[m] = s;
}

// q' = relu(x @ Pq + cq) + eps ; k' = relu(x @ Pk + ck) + eps   (NN, z selects)
__global__ void __launch_bounds__(256) k_qkprime(const float* __restrict__ x) {
    const float* Bm = blockIdx.z ? g_Pk : g_Pq;
    const float* ev = blockIdx.z ? g_ck : g_cq;
    float* C = blockIdx.z ? g_kp : g_qp;
    sgemm_body<0, 1>(x, Bm, C, ev, M_FEAT, D_DIM, M_FEAT, 0, D_DIM);
}

// colsum(k') two-stage deterministic reduction
__global__ void k_colsum1() {
    int m = threadIdx.x;                // 512 threads
    int n0 = blockIdx.x * CS_ROWS;
    float s = 0.f;
    for (int n = n0; n < n0 + CS_ROWS; n++) s += g_kp[n * M_FEAT + m];
    g_ks_part[blockIdx.x * M_FEAT + m] = s;
}
__global__ void k_colsum2() {
    int m = threadIdx.x;
    float s = 0.f;
    for (int c = 0; c < CS_BLOCKS; c++) s += g_ks_part[c * M_FEAT + m];
    g_ks[m] = s;
}

// kv partials: kv[m,d] = sum_n k'[n,m] * chi[n,d]   (TN, split-K)
__global__ void __launch_bounds__(256) k_kv(const float* __restrict__ chi) {
    float* C = g_kvpart + blockIdx.z * (M_FEAT * D_DIM);
    int k0 = blockIdx.z * KCHUNK;
    sgemm_body<1, 0>(g_kp, chi, C, nullptr, D_DIM, M_FEAT, D_DIM, k0, k0 + KCHUNK);
}

__global__ void k_kvred() {
    int i = blockIdx.x * blockDim.x + threadIdx.x;
    float s = 0.f;
#pragma unroll 8
    for (int z = 0; z < SPLITK; z++) s += g_kvpart[z * (M_FEAT * D_DIM) + i];
    g_kv[i] = s;
}

// den[n] = q'[n,:] . ks ; stabilize ; store 1/den
__global__ void k_den() {
    int n = blockIdx.x;
    int tid = threadIdx.x;              // 128 threads
    const float* q = g_qp + n * M_FEAT;
    float s = 0.f;
    for (int m = tid; m < M_FEAT; m += 128) s += q[m] * g_ks[m];
#pragma unroll
    for (int o = 16; o; o >>= 1) s += __shfl_down_sync(0xffffffffu, s, o);
    __shared__ float ws[4];
    if ((tid & 31) == 0) ws[tid >> 5] = s;
    __syncthreads();
    if (tid == 0) {
        float d = ws[0] + ws[1] + ws[2] + ws[3];
        if (fabsf(d) <= NSTAB) d += 2.f * NSTAB;
        g_invden[n] = 1.f / d;
    }
}

// out = (q' @ kv) * invden[row]   (NN, fused scale epilogue)
__global__ void __launch_bounds__(256) k_num(float* __restrict__ out) {
    sgemm_body<0, 2>(g_qp, g_kv, out, g_invden, D_DIM, M_FEAT, D_DIM, 0, M_FEAT);
}

// ---------------- launch ----------------
extern "C" void kernel_launch(void* const* d_in, const int* in_sizes, int n_in,
                              void* d_out, int out_size) {
    const float* chi  = (const float*)d_in[0];
    const float* x    = (const float*)d_in[1];
    const float* Wq   = (const float*)d_in[2];
    const float* bq   = (const float*)d_in[3];
    const float* Wk   = (const float*)d_in[4];
    const float* bk   = (const float*)d_in[5];
    const float* proj = (const float*)d_in[6];
    float* out = (float*)d_out;

    k_proj   <<<dim3(M_FEAT / BN, D_DIM / BM, 2), 256>>>(Wq, Wk, proj);
    k_bias   <<<dim3(2, 2), 256>>>(bq, bk, proj);
    k_qkprime<<<dim3(M_FEAT / BN, N_PTS / BM, 2), 256>>>(x);
    k_colsum1<<<CS_BLOCKS, 512>>>();
    k_colsum2<<<1, 512>>>();
    k_kv     <<<dim3(D_DIM / BN, M_FEAT / BM, SPLITK), 256>>>(chi);
    k_kvred  <<<(M_FEAT * D_DIM) / 256, 256>>>();
    k_den    <<<N_PTS, 128>>>();
    k_num    <<<dim3(D_DIM / BN, N_PTS / BM), 256>>>(out);
}

// round 4
// speedup vs baseline: 2.0650x; 2.0650x over previous
#include <cuda_runtime.h>
#include <cstdint>
#include <math.h>

// ---------------- problem constants ----------------
#define N_PTS 32768
#define D_DIM 512
#define M_FEAT 512
#define KEPS 0.001f
#define NSTAB 1e-6f
#define KV_SPLIT 16

// ---------------- scratch (device globals; no allocations) ----------------
__device__ float g_xr[(size_t)N_PTS * D_DIM];       // tf32-rounded x
__device__ float g_Bq[M_FEAT * D_DIM];              // Bq[m,j] = sum_d proj[m,d] Wq[j,d]  (tf32)
__device__ float g_Bk[M_FEAT * D_DIM];
__device__ float g_cq[M_FEAT];
__device__ float g_ck[M_FEAT];
__device__ float g_qp[(size_t)N_PTS * M_FEAT];      // q' [n,m]  (tf32)
__device__ float g_kpT[(size_t)M_FEAT * N_PTS];     // k'^T [m,n] (tf32)
__device__ float g_chiT[(size_t)D_DIM * N_PTS];     // chi^T [d,n] (tf32)
__device__ float g_ks[M_FEAT];
__device__ float g_kvpart[(size_t)KV_SPLIT * D_DIM * M_FEAT];
__device__ float g_kvT[D_DIM * M_FEAT];             // kvT [d,m] (tf32)
__device__ float g_invden[N_PTS];

// ---------------- helpers ----------------
__device__ __forceinline__ uint32_t smem_u32(const void* p) {
    uint32_t a;
    asm("{ .reg .u64 t; cvta.to.shared.u64 t, %1; cvt.u32.u64 %0, t; }" : "=r"(a) : "l"(p));
    return a;
}
__device__ __forceinline__ uint32_t tf32_bits(float x) {
    uint32_t u; asm("cvt.rna.tf32.f32 %0, %1;" : "=r"(u) : "f"(x)); return u;
}
__device__ __forceinline__ float to_tf32(float x) { return __uint_as_float(tf32_bits(x)); }

__device__ __forceinline__ void cp_async16(uint32_t saddr, const void* gptr) {
    asm volatile("cp.async.cg.shared.global [%0], [%1], 16;" :: "r"(saddr), "l"(gptr) : "memory");
}
__device__ __forceinline__ void cp_commit() { asm volatile("cp.async.commit_group;" ::: "memory"); }
template<int N>
__device__ __forceinline__ void cp_wait() { asm volatile("cp.async.wait_group %0;" :: "n"(N) : "memory"); }

__device__ __forceinline__ void mma_tf32(float* c, const uint32_t* a, const uint32_t* b) {
    asm volatile(
        "mma.sync.aligned.m16n8k8.row.col.f32.tf32.tf32.f32 "
        "{%0,%1,%2,%3}, {%4,%5,%6,%7}, {%8,%9}, {%0,%1,%2,%3};"
        : "+f"(c[0]), "+f"(c[1]), "+f"(c[2]), "+f"(c[3])
        : "r"(a[0]), "r"(a[1]), "r"(a[2]), "r"(a[3]), "r"(b[0]), "r"(b[1]));
}

// ---------------- tf32 mma.sync GEMM ----------------
// C[M,N] = A[M,K] * B[N,K]^T, all K-contiguous. 128x128x16 tile, 256 thr.
// EPI: 0 plain fp32 store; 1 relu(acc+ev[col])+eps -> tf32; 2 acc*ev[row]
#define LDK 20   // padded smem row stride (floats): conflict-free fragment LDS

template<int EPI, bool TRANS>
__global__ void __launch_bounds__(256, 2) gemm_tf32(
    const float* __restrict__ A, const float* __restrict__ B,
    float* __restrict__ C, const float* __restrict__ ev,
    int ldA, int ldB, int ldC, int kLen, size_t zStrideC, int kPerZ)
{
    __shared__ float As[2][128 * LDK];
    __shared__ float Bs[2][128 * LDK];

    const int tid = threadIdx.x;
    const int wid = tid >> 5, lane = tid & 31;
    const int wr = wid & 3, wc = wid >> 2;       // 4 (M) x 2 (N) warps
    const int mW = wr * 32, nW = wc * 64;
    const int rowBase = blockIdx.y * 128;
    const int colBase = blockIdx.x * 128;
    const int kBeg = blockIdx.z * kPerZ;
    C += (size_t)blockIdx.z * zStrideC;

    // staging: 512 16B-chunks per operand; each thread does 2 per operand
    const int srow = tid >> 2;                    // 0..63 (+64 on second iter? no: c>>2)
    (void)srow;

    auto stage = [&](int buf, int kb) {
#pragma unroll
        for (int i = 0; i < 2; i++) {
            const int c = tid + i * 256;
            const int row = c >> 2;
            const int kc = (c & 3) * 4;
            cp_async16(smem_u32(&As[buf][row * LDK + kc]),
                       A + (size_t)(rowBase + row) * ldA + kb + kc);
            cp_async16(smem_u32(&Bs[buf][row * LDK + kc]),
                       B + (size_t)(colBase + row) * ldB + kb + kc);
        }
        cp_commit();
    };

    float acc[2][8][4];
#pragma unroll
    for (int mt = 0; mt < 2; mt++)
#pragma unroll
        for (int nt = 0; nt < 8; nt++)
#pragma unroll
            for (int j = 0; j < 4; j++) acc[mt][nt][j] = 0.f;

    const int nk = kLen >> 4;
    stage(0, kBeg);

    const int rr = lane >> 2, cc = lane & 3;

    for (int kt = 0; kt < nk; kt++) {
        if (kt + 1 < nk) {
            stage((kt + 1) & 1, kBeg + (kt + 1) * 16);
            cp_wait<1>();
        } else {
            cp_wait<0>();
        }
        __syncthreads();

        const float* as = As[kt & 1];
        const float* bs = Bs[kt & 1];
#pragma unroll
        for (int ks = 0; ks < 2; ks++) {
            const int kc = ks * 8;
            uint32_t a[2][4], b[8][2];
#pragma unroll
            for (int mt = 0; mt < 2; mt++) {
                const int r = mW + mt * 16 + rr;
                a[mt][0] = __float_as_uint(as[r * LDK + kc + cc]);
                a[mt][1] = __float_as_uint(as[(r + 8) * LDK + kc + cc]);
                a[mt][2] = __float_as_uint(as[r * LDK + kc + cc + 4]);
                a[mt][3] = __float_as_uint(as[(r + 8) * LDK + kc + cc + 4]);
            }
#pragma unroll
            for (int nt = 0; nt < 8; nt++) {
                const int n = nW + nt * 8 + rr;
                b[nt][0] = __float_as_uint(bs[n * LDK + kc + cc]);
                b[nt][1] = __float_as_uint(bs[n * LDK + kc + cc + 4]);
            }
#pragma unroll
            for (int mt = 0; mt < 2; mt++)
#pragma unroll
                for (int nt = 0; nt < 8; nt++)
                    mma_tf32(acc[mt][nt], a[mt], b[nt]);
        }
        __syncthreads();
    }

    // ---------------- epilogue ----------------
#pragma unroll
    for (int mt = 0; mt < 2; mt++) {
        const int r0 = rowBase + mW + mt * 16 + rr;
#pragma unroll
        for (int half = 0; half < 2; half++) {
            const int r = r0 + half * 8;
            const float scale = (EPI == 2) ? ev[r] : 1.f;
#pragma unroll
            for (int nt = 0; nt < 8; nt++) {
                const int c0 = colBase + nW + nt * 8 + 2 * cc;
                float v0 = acc[mt][nt][half * 2 + 0];
                float v1 = acc[mt][nt][half * 2 + 1];
                if (EPI == 1) {
                    v0 = to_tf32(fmaxf(v0 + ev[c0], 0.f) + KEPS);
                    v1 = to_tf32(fmaxf(v1 + ev[c0 + 1], 0.f) + KEPS);
                } else if (EPI == 2) {
                    v0 *= scale; v1 *= scale;
                }
                if (TRANS) {
                    C[(size_t)c0 * ldC + r] = v0;
                    C[(size_t)(c0 + 1) * ldC + r] = v1;
                } else {
                    *(float2*)(C + (size_t)r * ldC + c0) = make_float2(v0, v1);
                }
            }
        }
    }
}

// ---------------- fp32 prep GEMM: Bq/Bk = proj @ W^T (tf32-rounded out) ----------------
#define BM 128
#define BN 128
#define BK 8
__global__ void __launch_bounds__(256) k_prep(const float* __restrict__ proj,
                                              const float* __restrict__ Wq,
                                              const float* __restrict__ Wk) {
    const float* B = blockIdx.z ? Wk : Wq;
    float* C = blockIdx.z ? g_Bk : g_Bq;
    __shared__ float As[BK][BM];
    __shared__ float Bs[BK][BN];
    const int tid = threadIdx.x;
    const int tx = tid & 15, ty = tid >> 4;
    const int rowBase = blockIdx.y * BM, colBase = blockIdx.x * BN;
    const int rA = tid >> 1, cA = (tid & 1) * 4;

    float acc[8][8];
#pragma unroll
    for (int i = 0; i < 8; i++)
#pragma unroll
        for (int j = 0; j < 8; j++) acc[i][j] = 0.f;

    for (int kb = 0; kb < D_DIM; kb += BK) {
        float4 av = *(const float4*)(proj + (rowBase + rA) * D_DIM + kb + cA);
        float4 bv = *(const float4*)(B + (colBase + rA) * D_DIM + kb + cA);
        __syncthreads();
        As[cA + 0][rA] = av.x; As[cA + 1][rA] = av.y; As[cA + 2][rA] = av.z; As[cA + 3][rA] = av.w;
        Bs[cA + 0][rA] = bv.x; Bs[cA + 1][rA] = bv.y; Bs[cA + 2][rA] = bv.z; Bs[cA + 3][rA] = bv.w;
        __syncthreads();
#pragma unroll
        for (int k = 0; k < BK; k++) {
            float a[8], b[8];
#pragma unroll
            for (int i = 0; i < 8; i++) a[i] = As[k][ty * 8 + i];
#pragma unroll
            for (int j = 0; j < 8; j++) b[j] = Bs[k][tx * 8 + j];
#pragma unroll
            for (int i = 0; i < 8; i++)
#pragma unroll
                for (int j = 0; j < 8; j++) acc[i][j] = fmaf(a[i], b[j], acc[i][j]);
        }
    }
#pragma unroll
    for (int i = 0; i < 8; i++) {
        float* cp = C + (rowBase + ty * 8 + i) * D_DIM + colBase + tx * 8;
#pragma unroll
        for (int j = 0; j < 8; j++) cp[j] = to_tf32(acc[i][j]);
    }
}

__global__ void k_bias(const float* __restrict__ bq, const float* __restrict__ bk,
                       const float* __restrict__ proj) {
    int m = blockIdx.x * blockDim.x + threadIdx.x;
    const float* b = blockIdx.y ? bk : bq;
    float* c = blockIdx.y ? g_ck : g_cq;
    float s = 0.f;
    for (int j = 0; j < D_DIM; j++) s += b[j] * proj[m * D_DIM + j];
    c[m] = s;
}

// tf32-round x into g_xr
__global__ void k_roundx(const float* __restrict__ x) {
    size_t i = ((size_t)blockIdx.x * 256 + threadIdx.x) * 4;
    float4 v = *(const float4*)(x + i);
    v.x = to_tf32(v.x); v.y = to_tf32(v.y); v.z = to_tf32(v.z); v.w = to_tf32(v.w);
    *(float4*)(g_xr + i) = v;
}

// chiT[d,n] = tf32(chi[n,d])
__global__ void k_chiT(const float* __restrict__ chi) {
    __shared__ float t[32][33];
    const int bx = blockIdx.x, by = blockIdx.y;
    const int x = threadIdx.x, y0 = threadIdx.y;
#pragma unroll
    for (int i = 0; i < 32; i += 8)
        t[y0 + i][x] = chi[(size_t)(bx * 32 + y0 + i) * D_DIM + by * 32 + x];
    __syncthreads();
#pragma unroll
    for (int i = 0; i < 32; i += 8)
        g_chiT[(size_t)(by * 32 + y0 + i) * N_PTS + bx * 32 + x] = to_tf32(t[x][y0 + i]);
}

// ks[m] = sum_n kpT[m,n]
__global__ void k_colsumT() {
    __shared__ float ws[8];
    const int m = blockIdx.x, tid = threadIdx.x;
    const float* p = g_kpT + (size_t)m * N_PTS;
    float s = 0.f;
    for (int n = tid; n < N_PTS; n += 256) s += p[n];
#pragma unroll
    for (int o = 16; o; o >>= 1) s += __shfl_down_sync(0xffffffffu, s, o);
    if ((tid & 31) == 0) ws[tid >> 5] = s;
    __syncthreads();
    if (tid == 0) {
        float t = 0.f;
        for (int i = 0; i < 8; i++) t += ws[i];
        g_ks[m] = t;
    }
}

__global__ void k_kvred() {
    int i = blockIdx.x * blockDim.x + threadIdx.x;
    float s = 0.f;
#pragma unroll
    for (int z = 0; z < KV_SPLIT; z++) s += g_kvpart[(size_t)z * D_DIM * M_FEAT + i];
    g_kvT[i] = to_tf32(s);
}

__global__ void k_den() {
    const int n = blockIdx.x, tid = threadIdx.x;
    const float* q = g_qp + (size_t)n * M_FEAT;
    float s = 0.f;
    for (int m = tid; m < M_FEAT; m += 128) s += q[m] * g_ks[m];
#pragma unroll
    for (int o = 16; o; o >>= 1) s += __shfl_down_sync(0xffffffffu, s, o);
    __shared__ float ws[4];
    if ((tid & 31) == 0) ws[tid >> 5] = s;
    __syncthreads();
    if (tid == 0) {
        float d = ws[0] + ws[1] + ws[2] + ws[3];
        if (fabsf(d) <= NSTAB) d += 2.f * NSTAB;
        g_invden[n] = 1.f / d;
    }
}

// ---------------- launch ----------------
extern "C" void kernel_launch(void* const* d_in, const int* in_sizes, int n_in,
                              void* d_out, int out_size) {
    const float* chi  = (const float*)d_in[0];
    const float* x    = (const float*)d_in[1];
    const float* Wq   = (const float*)d_in[2];
    const float* bq   = (const float*)d_in[3];
    const float* Wk   = (const float*)d_in[4];
    const float* bk   = (const float*)d_in[5];
    const float* proj = (const float*)d_in[6];
    float* out = (float*)d_out;

    void *p_xr, *p_qp, *p_kpT, *p_chiT, *p_Bq, *p_Bk, *p_cq, *p_ck, *p_kvpart, *p_kvT, *p_invden;
    cudaGetSymbolAddress(&p_xr, g_xr);
    cudaGetSymbolAddress(&p_qp, g_qp);
    cudaGetSymbolAddress(&p_kpT, g_kpT);
    cudaGetSymbolAddress(&p_chiT, g_chiT);
    cudaGetSymbolAddress(&p_Bq, g_Bq);
    cudaGetSymbolAddress(&p_Bk, g_Bk);
    cudaGetSymbolAddress(&p_cq, g_cq);
    cudaGetSymbolAddress(&p_ck, g_ck);
    cudaGetSymbolAddress(&p_kvpart, g_kvpart);
    cudaGetSymbolAddress(&p_kvT, g_kvT);
    cudaGetSymbolAddress(&p_invden, g_invden);

    // 1) prep: Bq/Bk (tf32) + bias projections + rounded x + chi transpose
    k_prep<<<dim3(D_DIM / BN, M_FEAT / BM, 2), 256>>>(proj, Wq, Wk);
    k_bias<<<dim3(2, 2), 256>>>(bq, bk, proj);
    k_roundx<<<(N_PTS * D_DIM) / (256 * 4), 256>>>(x);
    k_chiT<<<dim3(N_PTS / 32, D_DIM / 32), dim3(32, 8)>>>(chi);

    // 2) q' = relu(x@Bq^T + cq)+eps  [n,m] ; k'^T transposed store [m,n]
    gemm_tf32<1, false><<<dim3(M_FEAT / 128, N_PTS / 128), 256>>>(
        (const float*)p_xr, (const float*)p_Bq, (float*)p_qp, (const float*)p_cq,
        D_DIM, D_DIM, M_FEAT, D_DIM, 0, 0);
    gemm_tf32<1, true><<<dim3(M_FEAT / 128, N_PTS / 128), 256>>>(
        (const float*)p_xr, (const float*)p_Bk, (float*)p_kpT, (const float*)p_ck,
        D_DIM, D_DIM, N_PTS, D_DIM, 0, 0);

    // 3) ks = rowsum(kpT)
    k_colsumT<<<M_FEAT, 256>>>();

    // 4) kvT[d,m] = sum_n chiT[d,n]*kpT[m,n]  (split-K over n)
    gemm_tf32<0, false><<<dim3(M_FEAT / 128, D_DIM / 128, KV_SPLIT), 256>>>(
        (const float*)p_chiT, (const float*)p_kpT, (float*)p_kvpart, nullptr,
        N_PTS, N_PTS, M_FEAT, N_PTS / KV_SPLIT, (size_t)D_DIM * M_FEAT, N_PTS / KV_SPLIT);
    k_kvred<<<(D_DIM * M_FEAT) / 256, 256>>>();

    // 5) den -> invden
    k_den<<<N_PTS, 128>>>();

    // 6) out[n,d] = (q' @ kvT^T) * invden[n]
    gemm_tf32<2, false><<<dim3(D_DIM / 128, N_PTS / 128), 256>>>(
        (const float*)p_qp, (const float*)p_kvT, out, (const float*)p_invden,
        M_FEAT, M_FEAT, D_DIM, M_FEAT, 0, 0);
}

// round 5
// speedup vs baseline: 2.1796x; 1.0555x over previous
#include <cuda_runtime.h>
#include <cstdint>
#include <math.h>

// ---------------- problem constants ----------------
#define N_PTS 32768
#define D_DIM 512
#define M_FEAT 512
#define KEPS 0.001f
#define NSTAB 1e-6f
#define KV_SPLIT 16
#define CS_BLOCKS 128
#define CS_ROWS (N_PTS / CS_BLOCKS)

// ---------------- scratch (device globals; no allocations) ----------------
__device__ float g_xr[(size_t)N_PTS * D_DIM];       // tf32-rounded x [n,d]
__device__ float g_chiR[(size_t)N_PTS * D_DIM];     // tf32-rounded chi [n,d]
__device__ float g_Bq[M_FEAT * D_DIM];              // Bq[m,j] = sum_d proj[m,d] Wq[j,d] (tf32)
__device__ float g_Bk[M_FEAT * D_DIM];
__device__ float g_cq[M_FEAT];
__device__ float g_ck[M_FEAT];
__device__ float g_qp[(size_t)N_PTS * M_FEAT];      // q' [n,m]  (tf32)
__device__ float g_kp[(size_t)N_PTS * M_FEAT];      // k' [n,m]  (tf32)
__device__ float g_ks_part[CS_BLOCKS * M_FEAT];
__device__ float g_ks[M_FEAT];
__device__ float g_kvpart[(size_t)KV_SPLIT * D_DIM * M_FEAT];
__device__ float g_kvT[D_DIM * M_FEAT];             // kvT [d,m] (tf32)
__device__ float g_invden[N_PTS];

// ---------------- helpers ----------------
__device__ __forceinline__ uint32_t smem_u32(const void* p) {
    uint32_t a;
    asm("{ .reg .u64 t; cvta.to.shared.u64 t, %1; cvt.u32.u64 %0, t; }" : "=r"(a) : "l"(p));
    return a;
}
__device__ __forceinline__ uint32_t tf32_bits(float x) {
    uint32_t u; asm("cvt.rna.tf32.f32 %0, %1;" : "=r"(u) : "f"(x)); return u;
}
__device__ __forceinline__ float to_tf32(float x) { return __uint_as_float(tf32_bits(x)); }

__device__ __forceinline__ void cp_async16(uint32_t saddr, const void* gptr) {
    asm volatile("cp.async.cg.shared.global [%0], [%1], 16;" :: "r"(saddr), "l"(gptr) : "memory");
}
__device__ __forceinline__ void cp_commit() { asm volatile("cp.async.commit_group;" ::: "memory"); }
template<int N>
__device__ __forceinline__ void cp_wait() { asm volatile("cp.async.wait_group %0;" :: "n"(N) : "memory"); }

__device__ __forceinline__ void mma_tf32(float* c, const uint32_t* a, const uint32_t* b) {
    asm volatile(
        "mma.sync.aligned.m16n8k8.row.col.f32.tf32.tf32.f32 "
        "{%0,%1,%2,%3}, {%4,%5,%6,%7}, {%8,%9}, {%0,%1,%2,%3};"
        : "+f"(c[0]), "+f"(c[1]), "+f"(c[2]), "+f"(c[3])
        : "r"(a[0]), "r"(a[1]), "r"(a[2]), "r"(a[3]), "r"(b[0]), "r"(b[1]));
}

// ================= NT GEMM body: C[M,N] = A[M,K] * B[N,K]^T =================
// A, B row-major K-contiguous. 128x128x16 tile, 256 threads (4x2 warps).
// EPI: 0 plain fp32; 1 relu(acc+ev[col])+eps -> tf32; 2 acc*ev[row]
#define LDK 20

template<int EPI>
__device__ __forceinline__ void gemm_nt_body(
    const float* __restrict__ A, const float* __restrict__ B,
    float* __restrict__ C, const float* __restrict__ ev,
    int ldA, int ldB, int ldC, int kLen)
{
    __shared__ float As[2][128 * LDK];
    __shared__ float Bs[2][128 * LDK];

    const int tid = threadIdx.x;
    const int wid = tid >> 5, lane = tid & 31;
    const int wr = wid & 3, wc = wid >> 2;
    const int mW = wr * 32, nW = wc * 64;
    const int rowBase = blockIdx.y * 128;
    const int colBase = blockIdx.x * 128;

    auto stage = [&](int buf, int kb) {
#pragma unroll
        for (int i = 0; i < 2; i++) {
            const int c = tid + i * 256;
            const int row = c >> 2;
            const int kc = (c & 3) * 4;
            cp_async16(smem_u32(&As[buf][row * LDK + kc]),
                       A + (size_t)(rowBase + row) * ldA + kb + kc);
            cp_async16(smem_u32(&Bs[buf][row * LDK + kc]),
                       B + (size_t)(colBase + row) * ldB + kb + kc);
        }
        cp_commit();
    };

    float acc[2][8][4];
#pragma unroll
    for (int mt = 0; mt < 2; mt++)
#pragma unroll
        for (int nt = 0; nt < 8; nt++)
#pragma unroll
            for (int j = 0; j < 4; j++) acc[mt][nt][j] = 0.f;

    const int nk = kLen >> 4;
    stage(0, 0);
    const int rr = lane >> 2, cc = lane & 3;

    for (int kt = 0; kt < nk; kt++) {
        if (kt + 1 < nk) { stage((kt + 1) & 1, (kt + 1) * 16); cp_wait<1>(); }
        else             { cp_wait<0>(); }
        __syncthreads();

        const float* as = As[kt & 1];
        const float* bs = Bs[kt & 1];
#pragma unroll
        for (int ks = 0; ks < 2; ks++) {
            const int kc = ks * 8;
            uint32_t a[2][4], b[8][2];
#pragma unroll
            for (int mt = 0; mt < 2; mt++) {
                const int r = mW + mt * 16 + rr;
                a[mt][0] = __float_as_uint(as[r * LDK + kc + cc]);
                a[mt][1] = __float_as_uint(as[(r + 8) * LDK + kc + cc]);
                a[mt][2] = __float_as_uint(as[r * LDK + kc + cc + 4]);
                a[mt][3] = __float_as_uint(as[(r + 8) * LDK + kc + cc + 4]);
            }
#pragma unroll
            for (int nt = 0; nt < 8; nt++) {
                const int n = nW + nt * 8 + rr;
                b[nt][0] = __float_as_uint(bs[n * LDK + kc + cc]);
                b[nt][1] = __float_as_uint(bs[n * LDK + kc + cc + 4]);
            }
#pragma unroll
            for (int mt = 0; mt < 2; mt++)
#pragma unroll
                for (int nt = 0; nt < 8; nt++)
                    mma_tf32(acc[mt][nt], a[mt], b[nt]);
        }
        __syncthreads();
    }

#pragma unroll
    for (int mt = 0; mt < 2; mt++) {
#pragma unroll
        for (int half = 0; half < 2; half++) {
            const int r = rowBase + mW + mt * 16 + rr + half * 8;
            const float scale = (EPI == 2) ? ev[r] : 1.f;
#pragma unroll
            for (int nt = 0; nt < 8; nt++) {
                const int c0 = colBase + nW + nt * 8 + 2 * cc;
                float v0 = acc[mt][nt][half * 2 + 0];
                float v1 = acc[mt][nt][half * 2 + 1];
                if (EPI == 1) {
                    v0 = to_tf32(fmaxf(v0 + ev[c0], 0.f) + KEPS);
                    v1 = to_tf32(fmaxf(v1 + ev[c0 + 1], 0.f) + KEPS);
                } else if (EPI == 2) { v0 *= scale; v1 *= scale; }
                *(float2*)(C + (size_t)r * ldC + c0) = make_float2(v0, v1);
            }
        }
    }
}

// q'/k' combined: z=0 -> qp (Bq,cq), z=1 -> kp (Bk,ck)
__global__ void __launch_bounds__(256, 2) k_gemm_qk() {
    const float* B  = blockIdx.z ? g_Bk : g_Bq;
    const float* ev = blockIdx.z ? g_ck : g_cq;
    float* C        = blockIdx.z ? g_kp : g_qp;
    gemm_nt_body<1>(g_xr, B, C, ev, D_DIM, D_DIM, M_FEAT, D_DIM);
}

// out[n,d] = (qp @ kvT^T) * invden[n]
__global__ void __launch_bounds__(256, 2) k_gemm_num(float* __restrict__ out) {
    gemm_nt_body<2>(g_qp, g_kvT, out, g_invden, M_FEAT, M_FEAT, D_DIM, M_FEAT);
}

// ================= TT GEMM (kv): kvT[d,m] = sum_n chiR[n,d] * kp[n,m] =================
// Both operands [n, 512] row-major; smem tiles stored [k=16][mn=128] pad 136.
#define LDT 136

__global__ void __launch_bounds__(256, 2) k_gemm_kv() {
    __shared__ float As[2][16 * LDT];
    __shared__ float Bs[2][16 * LDT];

    const int tid = threadIdx.x;
    const int wid = tid >> 5, lane = tid & 31;
    const int wr = wid & 3, wc = wid >> 2;
    const int mW = wr * 32, nW = wc * 64;
    const int rowBase = blockIdx.y * 128;   // d
    const int colBase = blockIdx.x * 128;   // m
    const int kBeg = blockIdx.z * (N_PTS / KV_SPLIT);
    float* C = g_kvpart + (size_t)blockIdx.z * D_DIM * M_FEAT;

    auto stage = [&](int buf, int kb) {
#pragma unroll
        for (int i = 0; i < 2; i++) {
            const int c = tid + i * 256;          // 0..511
            const int row = c >> 5;               // n-row 0..15
            const int col = (c & 31) * 4;         // 0..124
            cp_async16(smem_u32(&As[buf][row * LDT + col]),
                       g_chiR + (size_t)(kb + row) * D_DIM + rowBase + col);
            cp_async16(smem_u32(&Bs[buf][row * LDT + col]),
                       g_kp + (size_t)(kb + row) * M_FEAT + colBase + col);
        }
        cp_commit();
    };

    float acc[2][8][4];
#pragma unroll
    for (int mt = 0; mt < 2; mt++)
#pragma unroll
        for (int nt = 0; nt < 8; nt++)
#pragma unroll
            for (int j = 0; j < 4; j++) acc[mt][nt][j] = 0.f;

    const int nk = (N_PTS / KV_SPLIT) >> 4;      // 128
    stage(0, kBeg);
    const int rr = lane >> 2, cc = lane & 3;

    for (int kt = 0; kt < nk; kt++) {
        if (kt + 1 < nk) { stage((kt + 1) & 1, kBeg + (kt + 1) * 16); cp_wait<1>(); }
        else             { cp_wait<0>(); }
        __syncthreads();

        const float* as = As[kt & 1];
        const float* bs = Bs[kt & 1];
#pragma unroll
        for (int ks = 0; ks < 2; ks++) {
            const int kc = ks * 8;
            uint32_t a[2][4], b[8][2];
#pragma unroll
            for (int mt = 0; mt < 2; mt++) {
                const int r = mW + mt * 16 + rr;
                a[mt][0] = __float_as_uint(as[(kc + cc) * LDT + r]);
                a[mt][1] = __float_as_uint(as[(kc + cc) * LDT + r + 8]);
                a[mt][2] = __float_as_uint(as[(kc + cc + 4) * LDT + r]);
                a[mt][3] = __float_as_uint(as[(kc + cc + 4) * LDT + r + 8]);
            }
#pragma unroll
            for (int nt = 0; nt < 8; nt++) {
                const int n = nW + nt * 8 + rr;
                b[nt][0] = __float_as_uint(bs[(kc + cc) * LDT + n]);
                b[nt][1] = __float_as_uint(bs[(kc + cc + 4) * LDT + n]);
            }
#pragma unroll
            for (int mt = 0; mt < 2; mt++)
#pragma unroll
                for (int nt = 0; nt < 8; nt++)
                    mma_tf32(acc[mt][nt], a[mt], b[nt]);
        }
        __syncthreads();
    }

#pragma unroll
    for (int mt = 0; mt < 2; mt++) {
#pragma unroll
        for (int half = 0; half < 2; half++) {
            const int r = rowBase + mW + mt * 16 + rr + half * 8;
#pragma unroll
            for (int nt = 0; nt < 8; nt++) {
                const int c0 = colBase + nW + nt * 8 + 2 * cc;
                *(float2*)(C + (size_t)r * M_FEAT + c0) =
                    make_float2(acc[mt][nt][half * 2], acc[mt][nt][half * 2 + 1]);
            }
        }
    }
}

// ---------------- fp32 prep GEMM: Bq/Bk = proj @ W^T (tf32-rounded out) ----------------
#define BM 128
#define BN 128
#define BK 8
__global__ void __launch_bounds__(256) k_prep(const float* __restrict__ proj,
                                              const float* __restrict__ Wq,
                                              const float* __restrict__ Wk) {
    const float* B = blockIdx.z ? Wk : Wq;
    float* C = blockIdx.z ? g_Bk : g_Bq;
    __shared__ float As[BK][BM];
    __shared__ float Bs[BK][BN];
    const int tid = threadIdx.x;
    const int tx = tid & 15, ty = tid >> 4;
    const int rowBase = blockIdx.y * BM, colBase = blockIdx.x * BN;
    const int rA = tid >> 1, cA = (tid & 1) * 4;

    float acc[8][8];
#pragma unroll
    for (int i = 0; i < 8; i++)
#pragma unroll
        for (int j = 0; j < 8; j++) acc[i][j] = 0.f;

    for (int kb = 0; kb < D_DIM; kb += BK) {
        float4 av = *(const float4*)(proj + (rowBase + rA) * D_DIM + kb + cA);
        float4 bv = *(const float4*)(B + (colBase + rA) * D_DIM + kb + cA);
        __syncthreads();
        As[cA + 0][rA] = av.x; As[cA + 1][rA] = av.y; As[cA + 2][rA] = av.z; As[cA + 3][rA] = av.w;
        Bs[cA + 0][rA] = bv.x; Bs[cA + 1][rA] = bv.y; Bs[cA + 2][rA] = bv.z; Bs[cA + 3][rA] = bv.w;
        __syncthreads();
#pragma unroll
        for (int k = 0; k < BK; k++) {
            float a[8], b[8];
#pragma unroll
            for (int i = 0; i < 8; i++) a[i] = As[k][ty * 8 + i];
#pragma unroll
            for (int j = 0; j < 8; j++) b[j] = Bs[k][tx * 8 + j];
#pragma unroll
            for (int i = 0; i < 8; i++)
#pragma unroll
                for (int j = 0; j < 8; j++) acc[i][j] = fmaf(a[i], b[j], acc[i][j]);
        }
    }
#pragma unroll
    for (int i = 0; i < 8; i++) {
        float* cp = C + (rowBase + ty * 8 + i) * D_DIM + colBase + tx * 8;
#pragma unroll
        for (int j = 0; j < 8; j++) cp[j] = to_tf32(acc[i][j]);
    }
}

__global__ void k_bias(const float* __restrict__ bq, const float* __restrict__ bk,
                       const float* __restrict__ proj) {
    int m = blockIdx.x * blockDim.x + threadIdx.x;
    const float* b = blockIdx.y ? bk : bq;
    float* c = blockIdx.y ? g_ck : g_cq;
    float s = 0.f;
    for (int j = 0; j < D_DIM; j++) s += b[j] * proj[m * D_DIM + j];
    c[m] = s;
}

// round x -> g_xr (z=0), chi -> g_chiR (z=1)
__global__ void k_round2(const float* __restrict__ x, const float* __restrict__ chi) {
    const float* src = blockIdx.z ? chi : x;
    float* dst = blockIdx.z ? g_chiR : g_xr;
    size_t i = ((size_t)blockIdx.x * 256 + threadIdx.x) * 4;
    float4 v = *(const float4*)(src + i);
    v.x = to_tf32(v.x); v.y = to_tf32(v.y); v.z = to_tf32(v.z); v.w = to_tf32(v.w);
    *(float4*)(dst + i) = v;
}

// colsum of g_kp, two-stage deterministic
__global__ void k_colsum1() {
    int m = threadIdx.x;
    int n0 = blockIdx.x * CS_ROWS;
    float s = 0.f;
    for (int n = n0; n < n0 + CS_ROWS; n++) s += g_kp[(size_t)n * M_FEAT + m];
    g_ks_part[blockIdx.x * M_FEAT + m] = s;
}
__global__ void k_colsum2() {
    int m = threadIdx.x;
    float s = 0.f;
    for (int c = 0; c < CS_BLOCKS; c++) s += g_ks_part[c * M_FEAT + m];
    g_ks[m] = s;
}

__global__ void k_kvred() {
    int i = blockIdx.x * blockDim.x + threadIdx.x;
    float s = 0.f;
#pragma unroll
    for (int z = 0; z < KV_SPLIT; z++) s += g_kvpart[(size_t)z * D_DIM * M_FEAT + i];
    g_kvT[i] = to_tf32(s);
}

__global__ void k_den() {
    const int n = blockIdx.x, tid = threadIdx.x;
    const float* q = g_qp + (size_t)n * M_FEAT;
    float s = 0.f;
    for (int m = tid; m < M_FEAT; m += 128) s += q[m] * g_ks[m];
#pragma unroll
    for (int o = 16; o; o >>= 1) s += __shfl_down_sync(0xffffffffu, s, o);
    __shared__ float ws[4];
    if ((tid & 31) == 0) ws[tid >> 5] = s;
    __syncthreads();
    if (tid == 0) {
        float d = ws[0] + ws[1] + ws[2] + ws[3];
        if (fabsf(d) <= NSTAB) d += 2.f * NSTAB;
        g_invden[n] = 1.f / d;
    }
}

// ---------------- launch ----------------
extern "C" void kernel_launch(void* const* d_in, const int* in_sizes, int n_in,
                              void* d_out, int out_size) {
    const float* chi  = (const float*)d_in[0];
    const float* x    = (const float*)d_in[1];
    const float* Wq   = (const float*)d_in[2];
    const float* bq   = (const float*)d_in[3];
    const float* Wk   = (const float*)d_in[4];
    const float* bk   = (const float*)d_in[5];
    const float* proj = (const float*)d_in[6];
    float* out = (float*)d_out;

    // 1) prep Bq/Bk (tf32) ; bias projections
    k_prep<<<dim3(D_DIM / BN, M_FEAT / BM, 2), 256>>>(proj, Wq, Wk);
    k_bias<<<dim3(2, 2), 256>>>(bq, bk, proj);
    // 2) round x and chi to tf32
    k_round2<<<dim3((N_PTS * D_DIM) / (256 * 4), 1, 2), 256>>>(x, chi);
    // 3) q' and k' (combined, coalesced [n,m] outputs)
    k_gemm_qk<<<dim3(M_FEAT / 128, N_PTS / 128, 2), 256>>>();
    // 4) ks = colsum(k')
    k_colsum1<<<CS_BLOCKS, 512>>>();
    k_colsum2<<<1, 512>>>();
    // 5) kvT[d,m] via TT GEMM, split-K over n
    k_gemm_kv<<<dim3(M_FEAT / 128, D_DIM / 128, KV_SPLIT), 256>>>();
    k_kvred<<<(D_DIM * M_FEAT) / 256, 256>>>();
    // 6) den -> invden
    k_den<<<N_PTS, 128>>>();
    // 7) out = (q' @ kvT^T) * invden
    k_gemm_num<<<dim3(D_DIM / 128, N_PTS / 128), 256>>>(out);
}

// round 6
// speedup vs baseline: 2.3853x; 1.0944x over previous
#include <cuda_runtime.h>
#include <cstdint>
#include <math.h>

// ---------------- problem constants ----------------
#define N_PTS 32768
#define D_DIM 512
#define M_FEAT 512
#define KEPS 0.001f
#define NSTAB 1e-6f
#define KV_SPLIT 16
#define CS_BLOCKS 128
#define CS_ROWS (N_PTS / CS_BLOCKS)

// ---------------- scratch (device globals; no allocations) ----------------
__device__ float g_Bq[M_FEAT * D_DIM];              // Bq[m,j] = sum_d proj[m,d] Wq[j,d] (tf32)
__device__ float g_Bk[M_FEAT * D_DIM];
__device__ float g_cq[M_FEAT];
__device__ float g_ck[M_FEAT];
__device__ float g_qp[(size_t)N_PTS * M_FEAT];      // q' [n,m]  (tf32)
__device__ float g_kp[(size_t)N_PTS * M_FEAT];      // k' [n,m]  (tf32)
__device__ float g_ks_part[CS_BLOCKS * M_FEAT];
__device__ float g_ks[M_FEAT];
__device__ float g_kvpart[(size_t)KV_SPLIT * D_DIM * M_FEAT];
__device__ float g_kvT[D_DIM * M_FEAT];             // kvT [d,m] (tf32)

// ---------------- helpers ----------------
__device__ __forceinline__ uint32_t smem_u32(const void* p) {
    uint32_t a;
    asm("{ .reg .u64 t; cvta.to.shared.u64 t, %1; cvt.u32.u64 %0, t; }" : "=r"(a) : "l"(p));
    return a;
}
__device__ __forceinline__ uint32_t tf32_bits(float x) {
    uint32_t u; asm("cvt.rna.tf32.f32 %0, %1;" : "=r"(u) : "f"(x)); return u;
}
__device__ __forceinline__ float to_tf32(float x) { return __uint_as_float(tf32_bits(x)); }

__device__ __forceinline__ void cp_async16(uint32_t saddr, const void* gptr) {
    asm volatile("cp.async.cg.shared.global [%0], [%1], 16;" :: "r"(saddr), "l"(gptr) : "memory");
}
__device__ __forceinline__ void cp_commit() { asm volatile("cp.async.commit_group;" ::: "memory"); }
template<int N>
__device__ __forceinline__ void cp_wait() { asm volatile("cp.async.wait_group %0;" :: "n"(N) : "memory"); }

__device__ __forceinline__ void mma_tf32(float* c, const uint32_t* a, const uint32_t* b) {
    asm volatile(
        "mma.sync.aligned.m16n8k8.row.col.f32.tf32.tf32.f32 "
        "{%0,%1,%2,%3}, {%4,%5,%6,%7}, {%8,%9}, {%0,%1,%2,%3};"
        : "+f"(c[0]), "+f"(c[1]), "+f"(c[2]), "+f"(c[3])
        : "r"(a[0]), "r"(a[1]), "r"(a[2]), "r"(a[3]), "r"(b[0]), "r"(b[1]));
}

// ================= NT GEMM body: C[M,N] = A[M,K] * B[N,K]^T =================
// 128x128x16 tile, 256 threads (4x2 warps), 3-stage cp.async ring, 1 sync/iter.
// EPI: 1 = relu(acc+ev[col])+eps -> tf32 ; 2 = acc * (1/den), den fused from g_ks
// CVTA: round A fragments to tf32 (rna) after LDS.
#define LDK 20

template<int EPI, bool CVTA, bool DEN>
__device__ __forceinline__ void gemm_nt_body(
    const float* __restrict__ A, const float* __restrict__ B,
    float* __restrict__ C, const float* __restrict__ ev,
    int ldA, int ldB, int ldC, int kLen)
{
    extern __shared__ float dsm[];
    float* Asm = dsm;                       // [3][128*LDK]
    float* Bsm = dsm + 3 * 128 * LDK;
    __shared__ float kss[DEN ? 512 : 1];

    const int tid = threadIdx.x;
    const int wid = tid >> 5, lane = tid & 31;
    const int wr = wid & 3, wc = wid >> 2;
    const int mW = wr * 32, nW = wc * 64;
    const int rowBase = blockIdx.y * 128;
    const int colBase = blockIdx.x * 128;

    if (DEN) {
        kss[tid] = g_ks[tid];
        kss[tid + 256] = g_ks[tid + 256];
    }

    auto stage = [&](int buf, int kb) {
        float* as = Asm + buf * 128 * LDK;
        float* bs = Bsm + buf * 128 * LDK;
#pragma unroll
        for (int i = 0; i < 2; i++) {
            const int c = tid + i * 256;
            const int row = c >> 2;
            const int kc = (c & 3) * 4;
            cp_async16(smem_u32(as + row * LDK + kc),
                       A + (size_t)(rowBase + row) * ldA + kb + kc);
            cp_async16(smem_u32(bs + row * LDK + kc),
                       B + (size_t)(colBase + row) * ldB + kb + kc);
        }
        cp_commit();
    };

    float acc[2][8][4];
#pragma unroll
    for (int mt = 0; mt < 2; mt++)
#pragma unroll
        for (int nt = 0; nt < 8; nt++)
#pragma unroll
            for (int j = 0; j < 4; j++) acc[mt][nt][j] = 0.f;
    float den[2][2] = {{0.f, 0.f}, {0.f, 0.f}};

    const int nk = kLen >> 4;
    stage(0, 0);
    stage(1, 16);
    const int rr = lane >> 2, cc = lane & 3;

    for (int kt = 0; kt < nk; kt++) {
        cp_wait<1>();
        __syncthreads();
        if (kt + 2 < nk) stage((kt + 2) % 3, (kt + 2) * 16);

        const float* as = Asm + (kt % 3) * 128 * LDK;
        const float* bs = Bsm + (kt % 3) * 128 * LDK;
#pragma unroll
        for (int ks = 0; ks < 2; ks++) {
            const int kc = ks * 8;
            uint32_t a[2][4], b[8][2];
#pragma unroll
            for (int mt = 0; mt < 2; mt++) {
                const int r = mW + mt * 16 + rr;
                float a0 = as[r * LDK + kc + cc];
                float a1 = as[(r + 8) * LDK + kc + cc];
                float a2 = as[r * LDK + kc + cc + 4];
                float a3 = as[(r + 8) * LDK + kc + cc + 4];
                if (CVTA) {
                    a[mt][0] = tf32_bits(a0); a[mt][1] = tf32_bits(a1);
                    a[mt][2] = tf32_bits(a2); a[mt][3] = tf32_bits(a3);
                } else {
                    a[mt][0] = __float_as_uint(a0); a[mt][1] = __float_as_uint(a1);
                    a[mt][2] = __float_as_uint(a2); a[mt][3] = __float_as_uint(a3);
                }
            }
#pragma unroll
            for (int nt = 0; nt < 8; nt++) {
                const int n = nW + nt * 8 + rr;
                b[nt][0] = __float_as_uint(bs[n * LDK + kc + cc]);
                b[nt][1] = __float_as_uint(bs[n * LDK + kc + cc + 4]);
            }
            if (DEN) {
                const float k0v = kss[kt * 16 + kc + cc];
                const float k1v = kss[kt * 16 + kc + cc + 4];
#pragma unroll
                for (int mt = 0; mt < 2; mt++) {
                    den[mt][0] += __uint_as_float(a[mt][0]) * k0v
                                + __uint_as_float(a[mt][2]) * k1v;
                    den[mt][1] += __uint_as_float(a[mt][1]) * k0v
                                + __uint_as_float(a[mt][3]) * k1v;
                }
            }
#pragma unroll
            for (int mt = 0; mt < 2; mt++)
#pragma unroll
                for (int nt = 0; nt < 8; nt++)
                    mma_tf32(acc[mt][nt], a[mt], b[nt]);
        }
    }

    float inv[2][2];
    if (DEN) {
#pragma unroll
        for (int mt = 0; mt < 2; mt++)
#pragma unroll
            for (int h = 0; h < 2; h++) {
                float d = den[mt][h];
                d += __shfl_xor_sync(0xffffffffu, d, 1);
                d += __shfl_xor_sync(0xffffffffu, d, 2);
                if (fabsf(d) <= NSTAB) d += 2.f * NSTAB;
                inv[mt][h] = 1.f / d;
            }
    }

#pragma unroll
    for (int mt = 0; mt < 2; mt++) {
#pragma unroll
        for (int half = 0; half < 2; half++) {
            const int r = rowBase + mW + mt * 16 + rr + half * 8;
            const float scale = DEN ? inv[mt][half] : 1.f;
#pragma unroll
            for (int nt = 0; nt < 8; nt++) {
                const int c0 = colBase + nW + nt * 8 + 2 * cc;
                float v0 = acc[mt][nt][half * 2 + 0];
                float v1 = acc[mt][nt][half * 2 + 1];
                if (EPI == 1) {
                    v0 = to_tf32(fmaxf(v0 + ev[c0], 0.f) + KEPS);
                    v1 = to_tf32(fmaxf(v1 + ev[c0 + 1], 0.f) + KEPS);
                } else if (EPI == 2) { v0 *= scale; v1 *= scale; }
                *(float2*)(C + (size_t)r * ldC + c0) = make_float2(v0, v1);
            }
        }
    }
}

// q'/k' combined: z=0 -> qp (Bq,cq), z=1 -> kp (Bk,ck); A = raw x, rounded in-fragment
__global__ void __launch_bounds__(256, 2) k_gemm_qk(const float* __restrict__ x) {
    const float* B  = blockIdx.z ? g_Bk : g_Bq;
    const float* ev = blockIdx.z ? g_ck : g_cq;
    float* C        = blockIdx.z ? g_kp : g_qp;
    gemm_nt_body<1, true, false>(x, B, C, ev, D_DIM, D_DIM, M_FEAT, D_DIM);
}

// out[n,d] = (qp @ kvT^T) * 1/den[n], den fused
__global__ void __launch_bounds__(256, 2) k_gemm_num(float* __restrict__ out) {
    gemm_nt_body<2, false, true>(g_qp, g_kvT, out, nullptr, M_FEAT, M_FEAT, D_DIM, M_FEAT);
}

// ================= TT GEMM (kv): kvT[d,m] = sum_n chi[n,d] * kp[n,m] =================
// smem tiles [k=16][mn=128] pad 136, 3-stage ring, 1 sync/iter. chi rounded in-fragment.
#define LDT 136

__global__ void __launch_bounds__(256, 2) k_gemm_kv(const float* __restrict__ chi) {
    extern __shared__ float dsm[];
    float* Asm = dsm;                       // [3][16*LDT]
    float* Bsm = dsm + 3 * 16 * LDT;

    const int tid = threadIdx.x;
    const int wid = tid >> 5, lane = tid & 31;
    const int wr = wid & 3, wc = wid >> 2;
    const int mW = wr * 32, nW = wc * 64;
    const int rowBase = blockIdx.y * 128;   // d
    const int colBase = blockIdx.x * 128;   // m
    const int kBeg = blockIdx.z * (N_PTS / KV_SPLIT);
    float* C = g_kvpart + (size_t)blockIdx.z * D_DIM * M_FEAT;

    auto stage = [&](int buf, int kb) {
        float* as = Asm + buf * 16 * LDT;
        float* bs = Bsm + buf * 16 * LDT;
#pragma unroll
        for (int i = 0; i < 2; i++) {
            const int c = tid + i * 256;          // 0..511
            const int row = c >> 5;               // n-row 0..15
            const int col = (c & 31) * 4;         // 0..124
            cp_async16(smem_u32(as + row * LDT + col),
                       chi + (size_t)(kb + row) * D_DIM + rowBase + col);
            cp_async16(smem_u32(bs + row * LDT + col),
                       g_kp + (size_t)(kb + row) * M_FEAT + colBase + col);
        }
        cp_commit();
    };

    float acc[2][8][4];
#pragma unroll
    for (int mt = 0; mt < 2; mt++)
#pragma unroll
        for (int nt = 0; nt < 8; nt++)
#pragma unroll
            for (int j = 0; j < 4; j++) acc[mt][nt][j] = 0.f;

    const int nk = (N_PTS / KV_SPLIT) >> 4;      // 128
    stage(0, kBeg);
    stage(1, kBeg + 16);
    const int rr = lane >> 2, cc = lane & 3;

    for (int kt = 0; kt < nk; kt++) {
        cp_wait<1>();
        __syncthreads();
        if (kt + 2 < nk) stage((kt + 2) % 3, kBeg + (kt + 2) * 16);

        const float* as = Asm + (kt % 3) * 16 * LDT;
        const float* bs = Bsm + (kt % 3) * 16 * LDT;
#pragma unroll
        for (int ks = 0; ks < 2; ks++) {
            const int kc = ks * 8;
            uint32_t a[2][4], b[8][2];
#pragma unroll
            for (int mt = 0; mt < 2; mt++) {
                const int r = mW + mt * 16 + rr;
                a[mt][0] = tf32_bits(as[(kc + cc) * LDT + r]);
                a[mt][1] = tf32_bits(as[(kc + cc) * LDT + r + 8]);
                a[mt][2] = tf32_bits(as[(kc + cc + 4) * LDT + r]);
                a[mt][3] = tf32_bits(as[(kc + cc + 4) * LDT + r + 8]);
            }
#pragma unroll
            for (int nt = 0; nt < 8; nt++) {
                const int n = nW + nt * 8 + rr;
                b[nt][0] = __float_as_uint(bs[(kc + cc) * LDT + n]);
                b[nt][1] = __float_as_uint(bs[(kc + cc + 4) * LDT + n]);
            }
#pragma unroll
            for (int mt = 0; mt < 2; mt++)
#pragma unroll
                for (int nt = 0; nt < 8; nt++)
                    mma_tf32(acc[mt][nt], a[mt], b[nt]);
        }
    }

#pragma unroll
    for (int mt = 0; mt < 2; mt++) {
#pragma unroll
        for (int half = 0; half < 2; half++) {
            const int r = rowBase + mW + mt * 16 + rr + half * 8;
#pragma unroll
            for (int nt = 0; nt < 8; nt++) {
                const int c0 = colBase + nW + nt * 8 + 2 * cc;
                *(float2*)(C + (size_t)r * M_FEAT + c0) =
                    make_float2(acc[mt][nt][half * 2], acc[mt][nt][half * 2 + 1]);
            }
        }
    }
}

// ---------------- fp32 prep GEMM: Bq/Bk = proj @ W^T (tf32-rounded out) ----------------
#define BM 128
#define BN 128
#define BK 8
__global__ void __launch_bounds__(256) k_prep(const float* __restrict__ proj,
                                              const float* __restrict__ Wq,
                                              const float* __restrict__ Wk) {
    const float* B = blockIdx.z ? Wk : Wq;
    float* C = blockIdx.z ? g_Bk : g_Bq;
    __shared__ float As[BK][BM];
    __shared__ float Bs[BK][BN];
    const int tid = threadIdx.x;
    const int tx = tid & 15, ty = tid >> 4;
    const int rowBase = blockIdx.y * BM, colBase = blockIdx.x * BN;
    const int rA = tid >> 1, cA = (tid & 1) * 4;

    float acc[8][8];
#pragma unroll
    for (int i = 0; i < 8; i++)
#pragma unroll
        for (int j = 0; j < 8; j++) acc[i][j] = 0.f;

    for (int kb = 0; kb < D_DIM; kb += BK) {
        float4 av = *(const float4*)(proj + (rowBase + rA) * D_DIM + kb + cA);
        float4 bv = *(const float4*)(B + (colBase + rA) * D_DIM + kb + cA);
        __syncthreads();
        As[cA + 0][rA] = av.x; As[cA + 1][rA] = av.y; As[cA + 2][rA] = av.z; As[cA + 3][rA] = av.w;
        Bs[cA + 0][rA] = bv.x; Bs[cA + 1][rA] = bv.y; Bs[cA + 2][rA] = bv.z; Bs[cA + 3][rA] = bv.w;
        __syncthreads();
#pragma unroll
        for (int k = 0; k < BK; k++) {
            float a[8], b[8];
#pragma unroll
            for (int i = 0; i < 8; i++) a[i] = As[k][ty * 8 + i];
#pragma unroll
            for (int j = 0; j < 8; j++) b[j] = Bs[k][tx * 8 + j];
#pragma unroll
            for (int i = 0; i < 8; i++)
#pragma unroll
                for (int j = 0; j < 8; j++) acc[i][j] = fmaf(a[i], b[j], acc[i][j]);
        }
    }
#pragma unroll
    for (int i = 0; i < 8; i++) {
        float* cp = C + (rowBase + ty * 8 + i) * D_DIM + colBase + tx * 8;
#pragma unroll
        for (int j = 0; j < 8; j++) cp[j] = to_tf32(acc[i][j]);
    }
}

__global__ void k_bias(const float* __restrict__ bq, const float* __restrict__ bk,
                       const float* __restrict__ proj) {
    int m = blockIdx.x * blockDim.x + threadIdx.x;
    const float* b = blockIdx.y ? bk : bq;
    float* c = blockIdx.y ? g_ck : g_cq;
    float s = 0.f;
    for (int j = 0; j < D_DIM; j++) s += b[j] * proj[m * D_DIM + j];
    c[m] = s;
}

// colsum of g_kp, two-stage deterministic
__global__ void k_colsum1() {
    int m = threadIdx.x;
    int n0 = blockIdx.x * CS_ROWS;
    float s = 0.f;
    for (int n = n0; n < n0 + CS_ROWS; n++) s += g_kp[(size_t)n * M_FEAT + m];
    g_ks_part[blockIdx.x * M_FEAT + m] = s;
}
__global__ void k_colsum2() {
    int m = threadIdx.x;
    float s = 0.f;
    for (int c = 0; c < CS_BLOCKS; c++) s += g_ks_part[c * M_FEAT + m];
    g_ks[m] = s;
}

__global__ void k_kvred() {
    int i = blockIdx.x * blockDim.x + threadIdx.x;
    float s = 0.f;
#pragma unroll
    for (int z = 0; z < KV_SPLIT; z++) s += g_kvpart[(size_t)z * D_DIM * M_FEAT + i];
    g_kvT[i] = to_tf32(s);
}

// ---------------- launch ----------------
extern "C" void kernel_launch(void* const* d_in, const int* in_sizes, int n_in,
                              void* d_out, int out_size) {
    const float* chi  = (const float*)d_in[0];
    const float* x    = (const float*)d_in[1];
    const float* Wq   = (const float*)d_in[2];
    const float* bq   = (const float*)d_in[3];
    const float* Wk   = (const float*)d_in[4];
    const float* bk   = (const float*)d_in[5];
    const float* proj = (const float*)d_in[6];
    float* out = (float*)d_out;

    const int nt_smem = 3 * 2 * 128 * LDK * 4;   // 61440 B
    const int tt_smem = 3 * 2 * 16 * LDT * 4;    // 52224 B
    cudaFuncSetAttribute(k_gemm_qk,  cudaFuncAttributeMaxDynamicSharedMemorySize, nt_smem);
    cudaFuncSetAttribute(k_gemm_num, cudaFuncAttributeMaxDynamicSharedMemorySize, nt_smem);
    cudaFuncSetAttribute(k_gemm_kv,  cudaFuncAttributeMaxDynamicSharedMemorySize, tt_smem);

    // 1) prep Bq/Bk (tf32) ; bias projections
    k_prep<<<dim3(D_DIM / BN, M_FEAT / BM, 2), 256>>>(proj, Wq, Wk);
    k_bias<<<dim3(2, 2), 256>>>(bq, bk, proj);
    // 2) q' and k' (x rounded in-fragment; coalesced [n,m] outputs)
    k_gemm_qk<<<dim3(M_FEAT / 128, N_PTS / 128, 2), 256, nt_smem>>>(x);
    // 3) ks = colsum(k')
    k_colsum1<<<CS_BLOCKS, 512>>>();
    k_colsum2<<<1, 512>>>();
    // 4) kvT[d,m] via TT GEMM (chi rounded in-fragment), split-K over n
    k_gemm_kv<<<dim3(M_FEAT / 128, D_DIM / 128, KV_SPLIT), 256, tt_smem>>>(chi);
    k_kvred<<<(D_DIM * M_FEAT) / 256, 256>>>();
    // 5) out = (q' @ kvT^T) * 1/den, den fused into GEMM
    k_gemm_num<<<dim3(D_DIM / 128, N_PTS / 128), 256, nt_smem>>>(out);
}

// round 7
// speedup vs baseline: 3.2241x; 1.3517x over previous
#include <cuda_runtime.h>
#include <cuda_fp16.h>
#include <cstdint>
#include <math.h>

// ---------------- problem constants ----------------
#define N_PTS 32768
#define D_DIM 512
#define M_FEAT 512
#define KEPS 0.001f
#define NSTAB 1e-6f
#define KV_SPLIT 16
#define QK_YB (N_PTS / 128)     // 256

// ---------------- scratch (device globals; no allocations) ----------------
__device__ __half g_xh[(size_t)N_PTS * D_DIM];      // x rounded to fp16
__device__ __half g_Bqh[M_FEAT * D_DIM];            // Bq[m,j] (fp16)
__device__ __half g_Bkh[M_FEAT * D_DIM];
__device__ float g_cq[M_FEAT];
__device__ float g_ck[M_FEAT];
__device__ __half g_qph[(size_t)N_PTS * M_FEAT];    // q' (fp16)
__device__ float g_kp[(size_t)N_PTS * M_FEAT];      // k' (tf32-rounded fp32, for kv)
__device__ float g_ks_part[QK_YB * M_FEAT];
__device__ float g_ks[M_FEAT];
__device__ float g_kvpart[(size_t)KV_SPLIT * D_DIM * M_FEAT];
__device__ __half g_kvh[D_DIM * M_FEAT];            // kvT (fp16)

// ---------------- helpers ----------------
__device__ __forceinline__ uint32_t smem_u32(const void* p) {
    uint32_t a;
    asm("{ .reg .u64 t; cvta.to.shared.u64 t, %1; cvt.u32.u64 %0, t; }" : "=r"(a) : "l"(p));
    return a;
}
__device__ __forceinline__ uint32_t tf32_bits(float x) {
    uint32_t u; asm("cvt.rna.tf32.f32 %0, %1;" : "=r"(u) : "f"(x)); return u;
}
__device__ __forceinline__ float to_tf32(float x) { return __uint_as_float(tf32_bits(x)); }

__device__ __forceinline__ void cp_async16(uint32_t saddr, const void* gptr) {
    asm volatile("cp.async.cg.shared.global [%0], [%1], 16;" :: "r"(saddr), "l"(gptr) : "memory");
}
__device__ __forceinline__ void cp_commit() { asm volatile("cp.async.commit_group;" ::: "memory"); }
template<int N>
__device__ __forceinline__ void cp_wait() { asm volatile("cp.async.wait_group %0;" :: "n"(N) : "memory"); }

__device__ __forceinline__ void mma_f16(float* c, const uint32_t* a, const uint32_t* b) {
    asm volatile(
        "mma.sync.aligned.m16n8k16.row.col.f32.f16.f16.f32 "
        "{%0,%1,%2,%3}, {%4,%5,%6,%7}, {%8,%9}, {%0,%1,%2,%3};"
        : "+f"(c[0]), "+f"(c[1]), "+f"(c[2]), "+f"(c[3])
        : "r"(a[0]), "r"(a[1]), "r"(a[2]), "r"(a[3]), "r"(b[0]), "r"(b[1]));
}
__device__ __forceinline__ void mma_tf32(float* c, const uint32_t* a, const uint32_t* b) {
    asm volatile(
        "mma.sync.aligned.m16n8k8.row.col.f32.tf32.tf32.f32 "
        "{%0,%1,%2,%3}, {%4,%5,%6,%7}, {%8,%9}, {%0,%1,%2,%3};"
        : "+f"(c[0]), "+f"(c[1]), "+f"(c[2]), "+f"(c[3])
        : "r"(a[0]), "r"(a[1]), "r"(a[2]), "r"(a[3]), "r"(b[0]), "r"(b[1]));
}

// =================== fp16 NT GEMM core (shared by qk and num) ===================
// C tile 128x128, BK=32, 256 threads (4x2 warps, warp 32m x 64n), 4-stage ring.
#define H2S 20                      // smem row stride in half2 (16 data + 4 pad, 16B-aligned)
#define QK_STG (128 * H2S)          // half2 per operand-stage
#define QK_SMEM (4 * 2 * QK_STG * 4)

struct F16Frags { uint32_t a[2][4]; uint32_t b[8][2]; };

__device__ __forceinline__ void f16_load_frags(
    F16Frags& f, const half2* as, const half2* bs, int ks,
    int mW, int nW, int rr, int cc)
{
    const int kc2 = ks * 8;
#pragma unroll
    for (int mt = 0; mt < 2; mt++) {
        const int r = mW + mt * 16 + rr;
        f.a[mt][0] = *(const uint32_t*)&as[r * H2S + kc2 + cc];
        f.a[mt][1] = *(const uint32_t*)&as[(r + 8) * H2S + kc2 + cc];
        f.a[mt][2] = *(const uint32_t*)&as[r * H2S + kc2 + cc + 4];
        f.a[mt][3] = *(const uint32_t*)&as[(r + 8) * H2S + kc2 + cc + 4];
    }
#pragma unroll
    for (int nt = 0; nt < 8; nt++) {
        const int n = nW + nt * 8 + rr;
        f.b[nt][0] = *(const uint32_t*)&bs[n * H2S + kc2 + cc];
        f.b[nt][1] = *(const uint32_t*)&bs[n * H2S + kc2 + cc + 4];
    }
}

// ---------------- qk: q'/k' = relu(x @ B^T + c) + eps ----------------
// z=0 -> qph (fp16 out), z=1 -> kp (tf32 fp32 out) + fused column-sum partials
__global__ void __launch_bounds__(256, 2) k_gemm_qk() {
    extern __shared__ __align__(16) float dsm[];
    half2* Asm = (half2*)dsm;
    half2* Bsm = (half2*)dsm + 4 * QK_STG;
    __shared__ float scol[4][128];

    const int tid = threadIdx.x;
    const int wid = tid >> 5, lane = tid & 31;
    const int wr = wid & 3, wc = wid >> 2;
    const int mW = wr * 32, nW = wc * 64;
    const int rowBase = blockIdx.y * 128;
    const int colBase = blockIdx.x * 128;
    const bool isK = (blockIdx.z == 1);
    const __half* Bg = isK ? g_Bkh : g_Bqh;
    const float* ev = isK ? g_ck : g_cq;

    auto stage = [&](int buf, int kb) {
        half2* as = Asm + buf * QK_STG;
        half2* bs = Bsm + buf * QK_STG;
#pragma unroll
        for (int i = 0; i < 2; i++) {
            const int c = tid + i * 256;
            const int row = c >> 2;
            const int kc = (c & 3) * 8;      // half units
            cp_async16(smem_u32(as + row * H2S + (c & 3) * 4),
                       g_xh + (size_t)(rowBase + row) * D_DIM + kb + kc);
            cp_async16(smem_u32(bs + row * H2S + (c & 3) * 4),
                       Bg + (size_t)(colBase + row) * D_DIM + kb + kc);
        }
        cp_commit();
    };

    float acc[2][8][4];
#pragma unroll
    for (int mt = 0; mt < 2; mt++)
#pragma unroll
        for (int nt = 0; nt < 8; nt++)
#pragma unroll
            for (int j = 0; j < 4; j++) acc[mt][nt][j] = 0.f;

    const int nk = D_DIM / 32;   // 16
    stage(0, 0); stage(1, 32); stage(2, 64);
    const int rr = lane >> 2, cc = lane & 3;

    for (int kt = 0; kt < nk; kt++) {
        cp_wait<2>();
        __syncthreads();
        if (kt + 3 < nk) stage((kt + 3) & 3, (kt + 3) * 32);
        const half2* as = Asm + (kt & 3) * QK_STG;
        const half2* bs = Bsm + (kt & 3) * QK_STG;
#pragma unroll
        for (int ks = 0; ks < 2; ks++) {
            F16Frags f;
            f16_load_frags(f, as, bs, ks, mW, nW, rr, cc);
#pragma unroll
            for (int mt = 0; mt < 2; mt++)
#pragma unroll
                for (int nt = 0; nt < 8; nt++)
                    mma_f16(acc[mt][nt], f.a[mt], f.b[nt]);
        }
    }

    // epilogue: relu(acc + ev[col]) + eps
    if (!isK) {
#pragma unroll
        for (int mt = 0; mt < 2; mt++)
#pragma unroll
            for (int half_ = 0; half_ < 2; half_++) {
                const int r = rowBase + mW + mt * 16 + rr + half_ * 8;
#pragma unroll
                for (int nt = 0; nt < 8; nt++) {
                    const int c0 = colBase + nW + nt * 8 + 2 * cc;
                    float v0 = fmaxf(acc[mt][nt][half_ * 2] + ev[c0], 0.f) + KEPS;
                    float v1 = fmaxf(acc[mt][nt][half_ * 2 + 1] + ev[c0 + 1], 0.f) + KEPS;
                    *(half2*)(g_qph + (size_t)r * M_FEAT + c0) = __floats2half2_rn(v0, v1);
                }
            }
    } else {
        float cs[8][2];
#pragma unroll
        for (int nt = 0; nt < 8; nt++) { cs[nt][0] = 0.f; cs[nt][1] = 0.f; }
#pragma unroll
        for (int mt = 0; mt < 2; mt++)
#pragma unroll
            for (int half_ = 0; half_ < 2; half_++) {
                const int r = rowBase + mW + mt * 16 + rr + half_ * 8;
#pragma unroll
                for (int nt = 0; nt < 8; nt++) {
                    const int c0 = colBase + nW + nt * 8 + 2 * cc;
                    float v0 = to_tf32(fmaxf(acc[mt][nt][half_ * 2] + ev[c0], 0.f) + KEPS);
                    float v1 = to_tf32(fmaxf(acc[mt][nt][half_ * 2 + 1] + ev[c0 + 1], 0.f) + KEPS);
                    *(float2*)(g_kp + (size_t)r * M_FEAT + c0) = make_float2(v0, v1);
                    cs[nt][0] += v0; cs[nt][1] += v1;
                }
            }
        // reduce column partials over rr within warp (lanes xor 4,8,16)
#pragma unroll
        for (int nt = 0; nt < 8; nt++)
#pragma unroll
            for (int j = 0; j < 2; j++) {
                float s = cs[nt][j];
                s += __shfl_xor_sync(0xffffffffu, s, 4);
                s += __shfl_xor_sync(0xffffffffu, s, 8);
                s += __shfl_xor_sync(0xffffffffu, s, 16);
                cs[nt][j] = s;
            }
        if (rr == 0) {
#pragma unroll
            for (int nt = 0; nt < 8; nt++) {
                scol[wr][nW + nt * 8 + 2 * cc] = cs[nt][0];
                scol[wr][nW + nt * 8 + 2 * cc + 1] = cs[nt][1];
            }
        }
        __syncthreads();
        if (tid < 128)
            g_ks_part[blockIdx.y * M_FEAT + colBase + tid] =
                scol[0][tid] + scol[1][tid] + scol[2][tid] + scol[3][tid];
    }
}

// ---------------- num: out[n,d] = (qph @ kvh^T) * 1/den[n], den fused ----------------
__global__ void __launch_bounds__(256, 2) k_gemm_num(float* __restrict__ out) {
    extern __shared__ __align__(16) float dsm[];
    half2* Asm = (half2*)dsm;
    half2* Bsm = (half2*)dsm + 4 * QK_STG;
    __shared__ float kss[512];

    const int tid = threadIdx.x;
    const int wid = tid >> 5, lane = tid & 31;
    const int wr = wid & 3, wc = wid >> 2;
    const int mW = wr * 32, nW = wc * 64;
    const int rowBase = blockIdx.y * 128;
    const int colBase = blockIdx.x * 128;

    kss[tid] = g_ks[tid];
    kss[tid + 256] = g_ks[tid + 256];

    auto stage = [&](int buf, int kb) {
        half2* as = Asm + buf * QK_STG;
        half2* bs = Bsm + buf * QK_STG;
#pragma unroll
        for (int i = 0; i < 2; i++) {
            const int c = tid + i * 256;
            const int row = c >> 2;
            const int kc = (c & 3) * 8;
            cp_async16(smem_u32(as + row * H2S + (c & 3) * 4),
                       g_qph + (size_t)(rowBase + row) * M_FEAT + kb + kc);
            cp_async16(smem_u32(bs + row * H2S + (c & 3) * 4),
                       g_kvh + (size_t)(colBase + row) * M_FEAT + kb + kc);
        }
        cp_commit();
    };

    float acc[2][8][4];
#pragma unroll
    for (int mt = 0; mt < 2; mt++)
#pragma unroll
        for (int nt = 0; nt < 8; nt++)
#pragma unroll
            for (int j = 0; j < 4; j++) acc[mt][nt][j] = 0.f;
    float den[2][2] = {{0.f, 0.f}, {0.f, 0.f}};

    const int nk = M_FEAT / 32;  // 16
    stage(0, 0); stage(1, 32); stage(2, 64);
    const int rr = lane >> 2, cc = lane & 3;

    for (int kt = 0; kt < nk; kt++) {
        cp_wait<2>();
        __syncthreads();
        if (kt + 3 < nk) stage((kt + 3) & 3, (kt + 3) * 32);
        const half2* as = Asm + (kt & 3) * QK_STG;
        const half2* bs = Bsm + (kt & 3) * QK_STG;
#pragma unroll
        for (int ks = 0; ks < 2; ks++) {
            F16Frags f;
            f16_load_frags(f, as, bs, ks, mW, nW, rr, cc);
            // fused den: qp dot ks over this thread's k positions
            const int kbase = kt * 32 + ks * 16;
            const float2 kA = *(const float2*)&kss[kbase + 2 * cc];
            const float2 kB = *(const float2*)&kss[kbase + 8 + 2 * cc];
#pragma unroll
            for (int mt = 0; mt < 2; mt++) {
                float2 a0 = __half22float2(*(const half2*)&f.a[mt][0]);
                float2 a1 = __half22float2(*(const half2*)&f.a[mt][1]);
                float2 a2 = __half22float2(*(const half2*)&f.a[mt][2]);
                float2 a3 = __half22float2(*(const half2*)&f.a[mt][3]);
                den[mt][0] += a0.x * kA.x + a0.y * kA.y + a2.x * kB.x + a2.y * kB.y;
                den[mt][1] += a1.x * kA.x + a1.y * kA.y + a3.x * kB.x + a3.y * kB.y;
            }
#pragma unroll
            for (int mt = 0; mt < 2; mt++)
#pragma unroll
                for (int nt = 0; nt < 8; nt++)
                    mma_f16(acc[mt][nt], f.a[mt], f.b[nt]);
        }
    }

    float inv[2][2];
#pragma unroll
    for (int mt = 0; mt < 2; mt++)
#pragma unroll
        for (int h = 0; h < 2; h++) {
            float d = den[mt][h];
            d += __shfl_xor_sync(0xffffffffu, d, 1);
            d += __shfl_xor_sync(0xffffffffu, d, 2);
            if (fabsf(d) <= NSTAB) d += 2.f * NSTAB;
            inv[mt][h] = 1.f / d;
        }

#pragma unroll
    for (int mt = 0; mt < 2; mt++)
#pragma unroll
        for (int half_ = 0; half_ < 2; half_++) {
            const int r = rowBase + mW + mt * 16 + rr + half_ * 8;
            const float sc = inv[mt][half_];
#pragma unroll
            for (int nt = 0; nt < 8; nt++) {
                const int c0 = colBase + nW + nt * 8 + 2 * cc;
                *(float2*)(out + (size_t)r * D_DIM + c0) =
                    make_float2(acc[mt][nt][half_ * 2] * sc, acc[mt][nt][half_ * 2 + 1] * sc);
            }
        }
}

// =============== kv TT GEMM (tf32): kvT[d,m] = sum_n chi[n,d]*kp[n,m] ===============
// smem [k=32][mn=128] pad 136, 3-stage, BK=32, chi rounded in-fragment.
#define LDT 136
#define KV_STG (32 * LDT)
#define KV_SMEM (3 * 2 * KV_STG * 4)

__global__ void __launch_bounds__(256, 2) k_gemm_kv(const float* __restrict__ chi) {
    extern __shared__ float dsm[];
    float* Asm = dsm;
    float* Bsm = dsm + 3 * KV_STG;

    const int tid = threadIdx.x;
    const int wid = tid >> 5, lane = tid & 31;
    const int wr = wid & 3, wc = wid >> 2;
    const int mW = wr * 32, nW = wc * 64;
    const int rowBase = blockIdx.y * 128;   // d
    const int colBase = blockIdx.x * 128;   // m
    const int kBeg = blockIdx.z * (N_PTS / KV_SPLIT);
    float* C = g_kvpart + (size_t)blockIdx.z * D_DIM * M_FEAT;

    auto stage = [&](int buf, int kb) {
        float* as = Asm + buf * KV_STG;
        float* bs = Bsm + buf * KV_STG;
#pragma unroll
        for (int i = 0; i < 4; i++) {
            const int c = tid + i * 256;          // 0..1023
            const int row = c >> 5;               // n-row 0..31
            const int col = (c & 31) * 4;
            cp_async16(smem_u32(as + row * LDT + col),
                       chi + (size_t)(kb + row) * D_DIM + rowBase + col);
            cp_async16(smem_u32(bs + row * LDT + col),
                       g_kp + (size_t)(kb + row) * M_FEAT + colBase + col);
        }
        cp_commit();
    };

    float acc[2][8][4];
#pragma unroll
    for (int mt = 0; mt < 2; mt++)
#pragma unroll
        for (int nt = 0; nt < 8; nt++)
#pragma unroll
            for (int j = 0; j < 4; j++) acc[mt][nt][j] = 0.f;

    const int nk = (N_PTS / KV_SPLIT) / 32;      // 64
    stage(0, kBeg);
    stage(1, kBeg + 32);
    const int rr = lane >> 2, cc = lane & 3;

    for (int kt = 0; kt < nk; kt++) {
        cp_wait<1>();
        __syncthreads();
        if (kt + 2 < nk) stage((kt + 2) % 3, kBeg + (kt + 2) * 32);
        const float* as = Asm + (kt % 3) * KV_STG;
        const float* bs = Bsm + (kt % 3) * KV_STG;
#pragma unroll
        for (int ks = 0; ks < 4; ks++) {
            const int kc = ks * 8;
            uint32_t a[2][4], b[8][2];
#pragma unroll
            for (int mt = 0; mt < 2; mt++) {
                const int r = mW + mt * 16 + rr;
                a[mt][0] = tf32_bits(as[(kc + cc) * LDT + r]);
                a[mt][1] = tf32_bits(as[(kc + cc) * LDT + r + 8]);
                a[mt][2] = tf32_bits(as[(kc + cc + 4) * LDT + r]);
                a[mt][3] = tf32_bits(as[(kc + cc + 4) * LDT + r + 8]);
            }
#pragma unroll
            for (int nt = 0; nt < 8; nt++) {
                const int n = nW + nt * 8 + rr;
                b[nt][0] = __float_as_uint(bs[(kc + cc) * LDT + n]);
                b[nt][1] = __float_as_uint(bs[(kc + cc + 4) * LDT + n]);
            }
#pragma unroll
            for (int mt = 0; mt < 2; mt++)
#pragma unroll
                for (int nt = 0; nt < 8; nt++)
                    mma_tf32(acc[mt][nt], a[mt], b[nt]);
        }
    }

#pragma unroll
    for (int mt = 0; mt < 2; mt++)
#pragma unroll
        for (int half_ = 0; half_ < 2; half_++) {
            const int r = rowBase + mW + mt * 16 + rr + half_ * 8;
#pragma unroll
            for (int nt = 0; nt < 8; nt++) {
                const int c0 = colBase + nW + nt * 8 + 2 * cc;
                *(float2*)(C + (size_t)r * M_FEAT + c0) =
                    make_float2(acc[mt][nt][half_ * 2], acc[mt][nt][half_ * 2 + 1]);
            }
        }
}

// ---------------- prep GEMM: Bq/Bk = proj @ W^T -> fp16 ----------------
#define BM 128
#define BN 128
#define BK 8
__global__ void __launch_bounds__(256) k_prep(const float* __restrict__ proj,
                                              const float* __restrict__ Wq,
                                              const float* __restrict__ Wk) {
    const float* B = blockIdx.z ? Wk : Wq;
    __half* C = blockIdx.z ? g_Bkh : g_Bqh;
    __shared__ float As[BK][BM];
    __shared__ float Bs[BK][BN];
    const int tid = threadIdx.x;
    const int tx = tid & 15, ty = tid >> 4;
    const int rowBase = blockIdx.y * BM, colBase = blockIdx.x * BN;
    const int rA = tid >> 1, cA = (tid & 1) * 4;

    float acc[8][8];
#pragma unroll
    for (int i = 0; i < 8; i++)
#pragma unroll
        for (int j = 0; j < 8; j++) acc[i][j] = 0.f;

    for (int kb = 0; kb < D_DIM; kb += BK) {
        float4 av = *(const float4*)(proj + (rowBase + rA) * D_DIM + kb + cA);
        float4 bv = *(const float4*)(B + (colBase + rA) * D_DIM + kb + cA);
        __syncthreads();
        As[cA + 0][rA] = av.x; As[cA + 1][rA] = av.y; As[cA + 2][rA] = av.z; As[cA + 3][rA] = av.w;
        Bs[cA + 0][rA] = bv.x; Bs[cA + 1][rA] = bv.y; Bs[cA + 2][rA] = bv.z; Bs[cA + 3][rA] = bv.w;
        __syncthreads();
#pragma unroll
        for (int k = 0; k < BK; k++) {
            float a[8], b[8];
#pragma unroll
            for (int i = 0; i < 8; i++) a[i] = As[k][ty * 8 + i];
#pragma unroll
            for (int j = 0; j < 8; j++) b[j] = Bs[k][tx * 8 + j];
#pragma unroll
            for (int i = 0; i < 8; i++)
#pragma unroll
                for (int j = 0; j < 8; j++) acc[i][j] = fmaf(a[i], b[j], acc[i][j]);
        }
    }
#pragma unroll
    for (int i = 0; i < 8; i++) {
        __half* cp = C + (rowBase + ty * 8 + i) * D_DIM + colBase + tx * 8;
#pragma unroll
        for (int j = 0; j < 8; j++) cp[j] = __float2half_rn(acc[i][j]);
    }
}

__global__ void k_bias(const float* __restrict__ bq, const float* __restrict__ bk,
                       const float* __restrict__ proj) {
    int m = blockIdx.x * blockDim.x + threadIdx.x;
    const float* b = blockIdx.y ? bk : bq;
    float* c = blockIdx.y ? g_ck : g_cq;
    float s = 0.f;
    for (int j = 0; j < D_DIM; j++) s += b[j] * proj[m * D_DIM + j];
    c[m] = s;
}

// x -> fp16
__global__ void k_cvt(const float* __restrict__ x) {
    size_t i = ((size_t)blockIdx.x * 256 + threadIdx.x) * 8;
    float4 v0 = *(const float4*)(x + i);
    float4 v1 = *(const float4*)(x + i + 4);
    half2 h0 = __floats2half2_rn(v0.x, v0.y);
    half2 h1 = __floats2half2_rn(v0.z, v0.w);
    half2 h2 = __floats2half2_rn(v1.x, v1.y);
    half2 h3 = __floats2half2_rn(v1.z, v1.w);
    uint4 o = make_uint4(*(uint32_t*)&h0, *(uint32_t*)&h1, *(uint32_t*)&h2, *(uint32_t*)&h3);
    *(uint4*)(g_xh + i) = o;
}

// ks[m] = sum over 256 row-block partials
__global__ void k_colsum2() {
    int m = threadIdx.x;   // 512
    float s = 0.f;
    for (int y = 0; y < QK_YB; y++) s += g_ks_part[y * M_FEAT + m];
    g_ks[m] = s;
}

__global__ void k_kvred() {
    int i = blockIdx.x * blockDim.x + threadIdx.x;
    float s = 0.f;
#pragma unroll
    for (int z = 0; z < KV_SPLIT; z++) s += g_kvpart[(size_t)z * D_DIM * M_FEAT + i];
    g_kvh[i] = __float2half_rn(s);
}

// ---------------- launch ----------------
extern "C" void kernel_launch(void* const* d_in, const int* in_sizes, int n_in,
                              void* d_out, int out_size) {
    const float* chi  = (const float*)d_in[0];
    const float* x    = (const float*)d_in[1];
    const float* Wq   = (const float*)d_in[2];
    const float* bq   = (const float*)d_in[3];
    const float* Wk   = (const float*)d_in[4];
    const float* bk   = (const float*)d_in[5];
    const float* proj = (const float*)d_in[6];
    float* out = (float*)d_out;

    cudaFuncSetAttribute(k_gemm_qk,  cudaFuncAttributeMaxDynamicSharedMemorySize, QK_SMEM);
    cudaFuncSetAttribute(k_gemm_num, cudaFuncAttributeMaxDynamicSharedMemorySize, QK_SMEM);
    cudaFuncSetAttribute(k_gemm_kv,  cudaFuncAttributeMaxDynamicSharedMemorySize, KV_SMEM);

    // 1) prep Bq/Bk (fp16), bias projections, x -> fp16
    k_prep<<<dim3(D_DIM / BN, M_FEAT / BM, 2), 256>>>(proj, Wq, Wk);
    k_bias<<<dim3(2, 2), 256>>>(bq, bk, proj);
    k_cvt<<<(N_PTS * D_DIM) / (256 * 8), 256>>>(x);
    // 2) q' (fp16 out) and k' (fp32 tf32-rounded out + colsum partials)
    k_gemm_qk<<<dim3(M_FEAT / 128, N_PTS / 128, 2), 256, QK_SMEM>>>();
    k_colsum2<<<1, 512>>>();
    // 3) kvT via tf32 TT GEMM, split-K over n
    k_gemm_kv<<<dim3(M_FEAT / 128, D_DIM / 128, KV_SPLIT), 256, KV_SMEM>>>(chi);
    k_kvred<<<(D_DIM * M_FEAT) / 256, 256>>>();
    // 4) out = (q' @ kvT^T) * 1/den, den fused
    k_gemm_num<<<dim3(D_DIM / 128, N_PTS / 128), 256, QK_SMEM>>>(out);
}

// round 8
// speedup vs baseline: 3.5284x; 1.0944x over previous
#include <cuda_runtime.h>
#include <cuda_fp16.h>
#include <cstdint>
#include <math.h>

// ---------------- problem constants ----------------
#define N_PTS 32768
#define D_DIM 512
#define M_FEAT 512
#define KEPS 0.001f
#define NSTAB 1e-6f
#define KV_SPLIT 16
#define QK_YB (N_PTS / 128)     // 256

// ---------------- scratch ----------------
__device__ __half g_xh[(size_t)N_PTS * D_DIM];
__device__ __half g_chih[(size_t)N_PTS * D_DIM];
__device__ __half g_Bqh[M_FEAT * D_DIM];
__device__ __half g_Bkh[M_FEAT * D_DIM];
__device__ float g_cq[M_FEAT];
__device__ float g_ck[M_FEAT];
__device__ __half g_qph[(size_t)N_PTS * M_FEAT];
__device__ __half g_kph[(size_t)N_PTS * M_FEAT];
__device__ float g_ks_part[QK_YB * M_FEAT];
__device__ float g_ks[M_FEAT];
__device__ float g_kvpart[(size_t)KV_SPLIT * D_DIM * M_FEAT];
__device__ __half g_kvh[D_DIM * M_FEAT];

// ---------------- helpers ----------------
__device__ __forceinline__ uint32_t smem_u32(const void* p) {
    uint32_t a;
    asm("{ .reg .u64 t; cvta.to.shared.u64 t, %1; cvt.u32.u64 %0, t; }" : "=r"(a) : "l"(p));
    return a;
}
__device__ __forceinline__ void cp_async16(uint32_t saddr, const void* gptr) {
    asm volatile("cp.async.cg.shared.global [%0], [%1], 16;" :: "r"(saddr), "l"(gptr) : "memory");
}
__device__ __forceinline__ void cp_commit() { asm volatile("cp.async.commit_group;" ::: "memory"); }
template<int N>
__device__ __forceinline__ void cp_wait() { asm volatile("cp.async.wait_group %0;" :: "n"(N) : "memory"); }

__device__ __forceinline__ void mma_f16(float* c, const uint32_t* a, const uint32_t* b) {
    asm volatile(
        "mma.sync.aligned.m16n8k16.row.col.f32.f16.f16.f32 "
        "{%0,%1,%2,%3}, {%4,%5,%6,%7}, {%8,%9}, {%0,%1,%2,%3};"
        : "+f"(c[0]), "+f"(c[1]), "+f"(c[2]), "+f"(c[3])
        : "r"(a[0]), "r"(a[1]), "r"(a[2]), "r"(a[3]), "r"(b[0]), "r"(b[1]));
}
__device__ __forceinline__ void ldsm_x4(uint32_t& r0, uint32_t& r1, uint32_t& r2, uint32_t& r3,
                                        uint32_t addr) {
    asm volatile("ldmatrix.sync.aligned.m8n8.x4.shared.b16 {%0,%1,%2,%3}, [%4];"
                 : "=r"(r0), "=r"(r1), "=r"(r2), "=r"(r3) : "r"(addr));
}
__device__ __forceinline__ void ldsm_x4_t(uint32_t& r0, uint32_t& r1, uint32_t& r2, uint32_t& r3,
                                          uint32_t addr) {
    asm volatile("ldmatrix.sync.aligned.m8n8.x4.trans.shared.b16 {%0,%1,%2,%3}, [%4];"
                 : "=r"(r0), "=r"(r1), "=r"(r2), "=r"(r3) : "r"(addr));
}

// =================== NT fp16 GEMM layout constants ===================
// C tile 128x128, BK=32, 256 thr (4m x 2n warps, warp 32m x 64n), 4-stage ring.
#define LQH 40                       // smem row stride in halves (32 data + 8 pad)
#define QK_STG_H (128 * LQH)         // halves per operand-stage
#define QK_SMEM (4 * 2 * QK_STG_H * 2)

// ---------------- qk: q'/k' = relu(x @ B^T + c) + eps ----------------
__global__ void __launch_bounds__(256, 2) k_gemm_qk() {
    extern __shared__ __align__(16) char smraw[];
    __half* Asm = (__half*)smraw;
    __half* Bsm = Asm + 4 * QK_STG_H;
    __shared__ float scol[4][128];

    const int tid = threadIdx.x;
    const int wid = tid >> 5, lane = tid & 31;
    const int wr = wid & 3, wc = wid >> 2;
    const int mW = wr * 32, nW = wc * 64;
    const int rowBase = blockIdx.y * 128;
    const int colBase = blockIdx.x * 128;
    const bool isK = (blockIdx.z == 1);
    const __half* Bg = isK ? g_Bkh : g_Bqh;
    const float* ev = isK ? g_ck : g_cq;

    const uint32_t aB = smem_u32(Asm), bB = smem_u32(Bsm);

    auto stage = [&](int buf, int kb) {
#pragma unroll
        for (int i = 0; i < 2; i++) {
            const int c = tid + i * 256;
            const int row = c >> 2;
            const int ch = (c & 3) * 8;
            cp_async16(aB + (buf * QK_STG_H + row * LQH + ch) * 2,
                       g_xh + (size_t)(rowBase + row) * D_DIM + kb + ch);
            cp_async16(bB + (buf * QK_STG_H + row * LQH + ch) * 2,
                       Bg + (size_t)(colBase + row) * D_DIM + kb + ch);
        }
        cp_commit();
    };

    float acc[2][8][4];
#pragma unroll
    for (int mt = 0; mt < 2; mt++)
#pragma unroll
        for (int nt = 0; nt < 8; nt++)
#pragma unroll
            for (int j = 0; j < 4; j++) acc[mt][nt][j] = 0.f;

    const int nk = D_DIM / 32;   // 16
    stage(0, 0); stage(1, 32); stage(2, 64);
    const int rr = lane >> 2, cc = lane & 3;
    const int lrow = lane & 15, lsel = (lane >> 4) << 3;

    for (int kt = 0; kt < nk; kt++) {
        cp_wait<2>();
        __syncthreads();
        if (kt + 3 < nk) stage((kt + 3) & 3, (kt + 3) * 32);
        const uint32_t abuf = aB + ((kt & 3) * QK_STG_H) * 2;
        const uint32_t bbuf = bB + ((kt & 3) * QK_STG_H) * 2;
#pragma unroll
        for (int ks = 0; ks < 2; ks++) {
            const int kcol = ks * 16 + lsel;
            uint32_t a[2][4], b[8][2];
#pragma unroll
            for (int mt = 0; mt < 2; mt++)
                ldsm_x4(a[mt][0], a[mt][1], a[mt][2], a[mt][3],
                        abuf + ((mW + mt * 16 + lrow) * LQH + kcol) * 2);
#pragma unroll
            for (int p = 0; p < 4; p++) {
                uint32_t r0, r1, r2, r3;
                ldsm_x4(r0, r1, r2, r3,
                        bbuf + ((nW + p * 16 + lrow) * LQH + kcol) * 2);
                b[2 * p][0] = r0; b[2 * p][1] = r2;
                b[2 * p + 1][0] = r1; b[2 * p + 1][1] = r3;
            }
#pragma unroll
            for (int mt = 0; mt < 2; mt++)
#pragma unroll
                for (int nt = 0; nt < 8; nt++)
                    mma_f16(acc[mt][nt], a[mt], b[nt]);
        }
    }

    if (!isK) {
#pragma unroll
        for (int mt = 0; mt < 2; mt++)
#pragma unroll
            for (int hf = 0; hf < 2; hf++) {
                const int r = rowBase + mW + mt * 16 + rr + hf * 8;
#pragma unroll
                for (int nt = 0; nt < 8; nt++) {
                    const int c0 = colBase + nW + nt * 8 + 2 * cc;
                    float v0 = fmaxf(acc[mt][nt][hf * 2] + ev[c0], 0.f) + KEPS;
                    float v1 = fmaxf(acc[mt][nt][hf * 2 + 1] + ev[c0 + 1], 0.f) + KEPS;
                    *(half2*)(g_qph + (size_t)r * M_FEAT + c0) = __floats2half2_rn(v0, v1);
                }
            }
    } else {
        float cs[8][2];
#pragma unroll
        for (int nt = 0; nt < 8; nt++) { cs[nt][0] = 0.f; cs[nt][1] = 0.f; }
#pragma unroll
        for (int mt = 0; mt < 2; mt++)
#pragma unroll
            for (int hf = 0; hf < 2; hf++) {
                const int r = rowBase + mW + mt * 16 + rr + hf * 8;
#pragma unroll
                for (int nt = 0; nt < 8; nt++) {
                    const int c0 = colBase + nW + nt * 8 + 2 * cc;
                    float v0 = fmaxf(acc[mt][nt][hf * 2] + ev[c0], 0.f) + KEPS;
                    float v1 = fmaxf(acc[mt][nt][hf * 2 + 1] + ev[c0 + 1], 0.f) + KEPS;
                    *(half2*)(g_kph + (size_t)r * M_FEAT + c0) = __floats2half2_rn(v0, v1);
                    cs[nt][0] += v0; cs[nt][1] += v1;
                }
            }
#pragma unroll
        for (int nt = 0; nt < 8; nt++)
#pragma unroll
            for (int j = 0; j < 2; j++) {
                float s = cs[nt][j];
                s += __shfl_xor_sync(0xffffffffu, s, 4);
                s += __shfl_xor_sync(0xffffffffu, s, 8);
                s += __shfl_xor_sync(0xffffffffu, s, 16);
                cs[nt][j] = s;
            }
        if (rr == 0) {
#pragma unroll
            for (int nt = 0; nt < 8; nt++) {
                scol[wr][nW + nt * 8 + 2 * cc] = cs[nt][0];
                scol[wr][nW + nt * 8 + 2 * cc + 1] = cs[nt][1];
            }
        }
        __syncthreads();
        if (tid < 128)
            g_ks_part[blockIdx.y * M_FEAT + colBase + tid] =
                scol[0][tid] + scol[1][tid] + scol[2][tid] + scol[3][tid];
    }
}

// ---------------- num: out = (qph @ kvh^T) * 1/den, den fused ----------------
__global__ void __launch_bounds__(256, 2) k_gemm_num(float* __restrict__ out) {
    extern __shared__ __align__(16) char smraw[];
    __half* Asm = (__half*)smraw;
    __half* Bsm = Asm + 4 * QK_STG_H;
    __shared__ float kss[512];

    const int tid = threadIdx.x;
    const int wid = tid >> 5, lane = tid & 31;
    const int wr = wid & 3, wc = wid >> 2;
    const int mW = wr * 32, nW = wc * 64;
    const int rowBase = blockIdx.y * 128;
    const int colBase = blockIdx.x * 128;

    kss[tid] = g_ks[tid];
    kss[tid + 256] = g_ks[tid + 256];

    const uint32_t aB = smem_u32(Asm), bB = smem_u32(Bsm);

    auto stage = [&](int buf, int kb) {
#pragma unroll
        for (int i = 0; i < 2; i++) {
            const int c = tid + i * 256;
            const int row = c >> 2;
            const int ch = (c & 3) * 8;
            cp_async16(aB + (buf * QK_STG_H + row * LQH + ch) * 2,
                       g_qph + (size_t)(rowBase + row) * M_FEAT + kb + ch);
            cp_async16(bB + (buf * QK_STG_H + row * LQH + ch) * 2,
                       g_kvh + (size_t)(colBase + row) * M_FEAT + kb + ch);
        }
        cp_commit();
    };

    float acc[2][8][4];
#pragma unroll
    for (int mt = 0; mt < 2; mt++)
#pragma unroll
        for (int nt = 0; nt < 8; nt++)
#pragma unroll
            for (int j = 0; j < 4; j++) acc[mt][nt][j] = 0.f;
    float den[2][2] = {{0.f, 0.f}, {0.f, 0.f}};

    const int nk = M_FEAT / 32;  // 16
    stage(0, 0); stage(1, 32); stage(2, 64);
    const int rr = lane >> 2, cc = lane & 3;
    const int lrow = lane & 15, lsel = (lane >> 4) << 3;

    for (int kt = 0; kt < nk; kt++) {
        cp_wait<2>();
        __syncthreads();
        if (kt + 3 < nk) stage((kt + 3) & 3, (kt + 3) * 32);
        const uint32_t abuf = aB + ((kt & 3) * QK_STG_H) * 2;
        const uint32_t bbuf = bB + ((kt & 3) * QK_STG_H) * 2;
#pragma unroll
        for (int ks = 0; ks < 2; ks++) {
            const int kcol = ks * 16 + lsel;
            uint32_t a[2][4], b[8][2];
#pragma unroll
            for (int mt = 0; mt < 2; mt++)
                ldsm_x4(a[mt][0], a[mt][1], a[mt][2], a[mt][3],
                        abuf + ((mW + mt * 16 + lrow) * LQH + kcol) * 2);
#pragma unroll
            for (int p = 0; p < 4; p++) {
                uint32_t r0, r1, r2, r3;
                ldsm_x4(r0, r1, r2, r3,
                        bbuf + ((nW + p * 16 + lrow) * LQH + kcol) * 2);
                b[2 * p][0] = r0; b[2 * p][1] = r2;
                b[2 * p + 1][0] = r1; b[2 * p + 1][1] = r3;
            }
            const int kbase = kt * 32 + ks * 16;
            const float2 kA = *(const float2*)&kss[kbase + 2 * cc];
            const float2 kB = *(const float2*)&kss[kbase + 8 + 2 * cc];
#pragma unroll
            for (int mt = 0; mt < 2; mt++) {
                float2 a0 = __half22float2(*(const half2*)&a[mt][0]);
                float2 a1 = __half22float2(*(const half2*)&a[mt][1]);
                float2 a2 = __half22float2(*(const half2*)&a[mt][2]);
                float2 a3 = __half22float2(*(const half2*)&a[mt][3]);
                den[mt][0] += a0.x * kA.x + a0.y * kA.y + a2.x * kB.x + a2.y * kB.y;
                den[mt][1] += a1.x * kA.x + a1.y * kA.y + a3.x * kB.x + a3.y * kB.y;
            }
#pragma unroll
            for (int mt = 0; mt < 2; mt++)
#pragma unroll
                for (int nt = 0; nt < 8; nt++)
                    mma_f16(acc[mt][nt], a[mt], b[nt]);
        }
    }

    float inv[2][2];
#pragma unroll
    for (int mt = 0; mt < 2; mt++)
#pragma unroll
        for (int h = 0; h < 2; h++) {
            float d = den[mt][h];
            d += __shfl_xor_sync(0xffffffffu, d, 1);
            d += __shfl_xor_sync(0xffffffffu, d, 2);
            if (fabsf(d) <= NSTAB) d += 2.f * NSTAB;
            inv[mt][h] = 1.f / d;
        }

#pragma unroll
    for (int mt = 0; mt < 2; mt++)
#pragma unroll
        for (int hf = 0; hf < 2; hf++) {
            const int r = rowBase + mW + mt * 16 + rr + hf * 8;
            const float sc = inv[mt][hf];
#pragma unroll
            for (int nt = 0; nt < 8; nt++) {
                const int c0 = colBase + nW + nt * 8 + 2 * cc;
                *(float2*)(out + (size_t)r * D_DIM + c0) =
                    make_float2(acc[mt][nt][hf * 2] * sc, acc[mt][nt][hf * 2 + 1] * sc);
            }
        }
}

// ========== kv TT fp16 GEMM: kvT[d,m] = sum_n chih[n,d] * kph[n,m] ==========
// smem tiles [n=32 rows][128 cols] halves, stride 136; ldmatrix.trans frags.
#define LKV 136
#define KV_STG_H (32 * LKV)
#define KV_SMEM (3 * 2 * KV_STG_H * 2)

__global__ void __launch_bounds__(256, 2) k_gemm_kv() {
    extern __shared__ __align__(16) char smraw[];
    __half* Asm = (__half*)smraw;
    __half* Bsm = Asm + 3 * KV_STG_H;

    const int tid = threadIdx.x;
    const int wid = tid >> 5, lane = tid & 31;
    const int wr = wid & 3, wc = wid >> 2;
    const int mW = wr * 32, nW = wc * 64;
    const int rowBase = blockIdx.y * 128;   // d
    const int colBase = blockIdx.x * 128;   // m
    const int kBeg = blockIdx.z * (N_PTS / KV_SPLIT);
    float* C = g_kvpart + (size_t)blockIdx.z * D_DIM * M_FEAT;

    const uint32_t aB = smem_u32(Asm), bB = smem_u32(Bsm);

    auto stage = [&](int buf, int kb) {
#pragma unroll
        for (int i = 0; i < 2; i++) {
            const int c = tid + i * 256;          // 0..511
            const int row = c >> 4;               // n-row 0..31
            const int ch = (c & 15) * 8;          // halves col 0..120
            cp_async16(aB + (buf * KV_STG_H + row * LKV + ch) * 2,
                       g_chih + (size_t)(kb + row) * D_DIM + rowBase + ch);
            cp_async16(bB + (buf * KV_STG_H + row * LKV + ch) * 2,
                       g_kph + (size_t)(kb + row) * M_FEAT + colBase + ch);
        }
        cp_commit();
    };

    float acc[2][8][4];
#pragma unroll
    for (int mt = 0; mt < 2; mt++)
#pragma unroll
        for (int nt = 0; nt < 8; nt++)
#pragma unroll
            for (int j = 0; j < 4; j++) acc[mt][nt][j] = 0.f;

    const int nk = (N_PTS / KV_SPLIT) / 32;      // 64
    stage(0, kBeg);
    stage(1, kBeg + 32);
    const int rr = lane >> 2, cc = lane & 3;
    const int lrow = lane & 15, lsel = (lane >> 4) << 3;

    for (int kt = 0; kt < nk; kt++) {
        cp_wait<1>();
        __syncthreads();
        if (kt + 2 < nk) stage((kt + 2) % 3, kBeg + (kt + 2) * 32);
        const uint32_t abuf = aB + ((kt % 3) * KV_STG_H) * 2;
        const uint32_t bbuf = bB + ((kt % 3) * KV_STG_H) * 2;
#pragma unroll
        for (int ks = 0; ks < 2; ks++) {
            const int krow = ks * 16 + lrow;
            uint32_t a[2][4], b[8][2];
#pragma unroll
            for (int mt = 0; mt < 2; mt++) {
                uint32_t r0, r1, r2, r3;
                ldsm_x4_t(r0, r1, r2, r3,
                          abuf + (krow * LKV + mW + mt * 16 + lsel) * 2);
                a[mt][0] = r0; a[mt][1] = r2; a[mt][2] = r1; a[mt][3] = r3;
            }
#pragma unroll
            for (int p = 0; p < 4; p++) {
                uint32_t r0, r1, r2, r3;
                ldsm_x4_t(r0, r1, r2, r3,
                          bbuf + (krow * LKV + nW + p * 16 + lsel) * 2);
                b[2 * p][0] = r0; b[2 * p][1] = r1;
                b[2 * p + 1][0] = r2; b[2 * p + 1][1] = r3;
            }
#pragma unroll
            for (int mt = 0; mt < 2; mt++)
#pragma unroll
                for (int nt = 0; nt < 8; nt++)
                    mma_f16(acc[mt][nt], a[mt], b[nt]);
        }
    }

#pragma unroll
    for (int mt = 0; mt < 2; mt++)
#pragma unroll
        for (int hf = 0; hf < 2; hf++) {
            const int r = rowBase + mW + mt * 16 + rr + hf * 8;
#pragma unroll
            for (int nt = 0; nt < 8; nt++) {
                const int c0 = colBase + nW + nt * 8 + 2 * cc;
                *(float2*)(C + (size_t)r * M_FEAT + c0) =
                    make_float2(acc[mt][nt][hf * 2], acc[mt][nt][hf * 2 + 1]);
            }
        }
}

// ---------------- prep GEMM: Bq/Bk = proj @ W^T -> fp16 ----------------
#define BM 128
#define BN 128
#define BK 8
__global__ void __launch_bounds__(256) k_prep(const float* __restrict__ proj,
                                              const float* __restrict__ Wq,
                                              const float* __restrict__ Wk) {
    const float* B = blockIdx.z ? Wk : Wq;
    __half* C = blockIdx.z ? g_Bkh : g_Bqh;
    __shared__ float As[BK][BM];
    __shared__ float Bs[BK][BN];
    const int tid = threadIdx.x;
    const int tx = tid & 15, ty = tid >> 4;
    const int rowBase = blockIdx.y * BM, colBase = blockIdx.x * BN;
    const int rA = tid >> 1, cA = (tid & 1) * 4;

    float acc[8][8];
#pragma unroll
    for (int i = 0; i < 8; i++)
#pragma unroll
        for (int j = 0; j < 8; j++) acc[i][j] = 0.f;

    for (int kb = 0; kb < D_DIM; kb += BK) {
        float4 av = *(const float4*)(proj + (rowBase + rA) * D_DIM + kb + cA);
        float4 bv = *(const float4*)(B + (colBase + rA) * D_DIM + kb + cA);
        __syncthreads();
        As[cA + 0][rA] = av.x; As[cA + 1][rA] = av.y; As[cA + 2][rA] = av.z; As[cA + 3][rA] = av.w;
        Bs[cA + 0][rA] = bv.x; Bs[cA + 1][rA] = bv.y; Bs[cA + 2][rA] = bv.z; Bs[cA + 3][rA] = bv.w;
        __syncthreads();
#pragma unroll
        for (int k = 0; k < BK; k++) {
            float a[8], b[8];
#pragma unroll
            for (int i = 0; i < 8; i++) a[i] = As[k][ty * 8 + i];
#pragma unroll
            for (int j = 0; j < 8; j++) b[j] = Bs[k][tx * 8 + j];
#pragma unroll
            for (int i = 0; i < 8; i++)
#pragma unroll
                for (int j = 0; j < 8; j++) acc[i][j] = fmaf(a[i], b[j], acc[i][j]);
        }
    }
#pragma unroll
    for (int i = 0; i < 8; i++) {
        __half* cp = C + (rowBase + ty * 8 + i) * D_DIM + colBase + tx * 8;
#pragma unroll
        for (int j = 0; j < 8; j++) cp[j] = __float2half_rn(acc[i][j]);
    }
}

__global__ void k_bias(const float* __restrict__ bq, const float* __restrict__ bk,
                       const float* __restrict__ proj) {
    int m = blockIdx.x * blockDim.x + threadIdx.x;
    const float* b = blockIdx.y ? bk : bq;
    float* c = blockIdx.y ? g_ck : g_cq;
    float s = 0.f;
    for (int j = 0; j < D_DIM; j++) s += b[j] * proj[m * D_DIM + j];
    c[m] = s;
}

// x -> g_xh (z=0), chi -> g_chih (z=1)
__global__ void k_cvt(const float* __restrict__ x, const float* __restrict__ chi) {
    const float* src = blockIdx.z ? chi : x;
    __half* dst = blockIdx.z ? g_chih : g_xh;
    size_t i = ((size_t)blockIdx.x * 256 + threadIdx.x) * 8;
    float4 v0 = *(const float4*)(src + i);
    float4 v1 = *(const float4*)(src + i + 4);
    half2 h0 = __floats2half2_rn(v0.x, v0.y);
    half2 h1 = __floats2half2_rn(v0.z, v0.w);
    half2 h2 = __floats2half2_rn(v1.x, v1.y);
    half2 h3 = __floats2half2_rn(v1.z, v1.w);
    uint4 o = make_uint4(*(uint32_t*)&h0, *(uint32_t*)&h1, *(uint32_t*)&h2, *(uint32_t*)&h3);
    *(uint4*)(dst + i) = o;
}

__global__ void k_colsum2() {
    int m = threadIdx.x;   // 512
    float s = 0.f;
    for (int y = 0; y < QK_YB; y++) s += g_ks_part[y * M_FEAT + m];
    g_ks[m] = s;
}

__global__ void k_kvred() {
    int i = blockIdx.x * blockDim.x + threadIdx.x;
    float s = 0.f;
#pragma unroll
    for (int z = 0; z < KV_SPLIT; z++) s += g_kvpart[(size_t)z * D_DIM * M_FEAT + i];
    g_kvh[i] = __float2half_rn(s);
}

// ---------------- launch ----------------
extern "C" void kernel_launch(void* const* d_in, const int* in_sizes, int n_in,
                              void* d_out, int out_size) {
    const float* chi  = (const float*)d_in[0];
    const float* x    = (const float*)d_in[1];
    const float* Wq   = (const float*)d_in[2];
    const float* bq   = (const float*)d_in[3];
    const float* Wk   = (const float*)d_in[4];
    const float* bk   = (const float*)d_in[5];
    const float* proj = (const float*)d_in[6];
    float* out = (float*)d_out;

    cudaFuncSetAttribute(k_gemm_qk,  cudaFuncAttributeMaxDynamicSharedMemorySize, QK_SMEM);
    cudaFuncSetAttribute(k_gemm_num, cudaFuncAttributeMaxDynamicSharedMemorySize, QK_SMEM);
    cudaFuncSetAttribute(k_gemm_kv,  cudaFuncAttributeMaxDynamicSharedMemorySize, KV_SMEM);

    // 1) prep Bq/Bk (fp16), bias projections, x/chi -> fp16
    k_prep<<<dim3(D_DIM / BN, M_FEAT / BM, 2), 256>>>(proj, Wq, Wk);
    k_bias<<<dim3(2, 2), 256>>>(bq, bk, proj);
    k_cvt<<<dim3((N_PTS * D_DIM) / (256 * 8), 1, 2), 256>>>(x, chi);
    // 2) q'(fp16) / k'(fp16 + colsum partials)
    k_gemm_qk<<<dim3(M_FEAT / 128, N_PTS / 128, 2), 256, QK_SMEM>>>();
    k_colsum2<<<1, 512>>>();
    // 3) kvT via fp16 TT GEMM (ldmatrix.trans), split-K over n
    k_gemm_kv<<<dim3(M_FEAT / 128, D_DIM / 128, KV_SPLIT), 256, KV_SMEM>>>();
    k_kvred<<<(D_DIM * M_FEAT) / 256, 256>>>();
    // 4) out = (q' @ kvT^T) * 1/den, den fused
    k_gemm_num<<<dim3(D_DIM / 128, N_PTS / 128), 256, QK_SMEM>>>(out);
}